// round 1
// baseline (speedup 1.0000x reference)
#include <cuda_runtime.h>

#define NIN 8
#define H   128
#define BT  64     // samples per block
#define P   132    // padded row stride (floats), multiple of 4, stride mod 32 = 4
#define TPB 256

// smem sizes in floats
#define FWD_SMEM_F  (2*H*P + BT*P + BT*NIN + 2*H*NIN + 5*H)
#define GRAD_SMEM_F (FWD_SMEM_F + BT*P + BT*NIN)
#define FWD_SMEM_B  (FWD_SMEM_F * 4)
#define GRAD_SMEM_B (GRAD_SMEM_F * 4)

template <bool GRAD>
__global__ __launch_bounds__(TPB)
void net_kernel(const float* __restrict__ x,     // (n, 8)
                const float* __restrict__ xdot,  // (n, 8) or null
                const float* __restrict__ w11, const float* __restrict__ b11,
                const float* __restrict__ w21, const float* __restrict__ b21,
                const float* __restrict__ w12, const float* __restrict__ b12,
                const float* __restrict__ w22, const float* __restrict__ b22,
                const float* __restrict__ wout,
                float* __restrict__ out_v,
                float* __restrict__ out_g)
{
    extern __shared__ float sm[];
    float* sW1 = sm;            // [H][P]   w1_2, row o, cols h
    float* sW2 = sW1 + H * P;   // [H][P]   w2_2
    float* sY  = sW2 + H * P;   // [BT][P]  hidden y, row b, cols h
    float* p   = sY + BT * P;
    float* sDY = p;             // [BT][P] (GRAD only)
    if (GRAD) p += BT * P;
    float* sXt = p; p += BT * NIN;     // [NIN][BT] transposed x tile
    float* sXd = p; if (GRAD) p += BT * NIN;
    float* sW11 = p; p += H * NIN;
    float* sW21 = p; p += H * NIN;
    float* sB11 = p; p += H;
    float* sB21 = p; p += H;
    float* sB12 = p; p += H;
    float* sB22 = p; p += H;
    float* sWout = p;

    const int tid = threadIdx.x;

    // ---- Stage A: load weights & inputs into smem ----
    {
        const float4* g1 = (const float4*)w12;
        const float4* g2 = (const float4*)w22;
        #pragma unroll
        for (int it = 0; it < (H * H / 4) / TPB; it++) {
            int q = tid + it * TPB;           // q in [0, 4096)
            int o  = q >> 5;                  // q / 32
            int h4 = q & 31;
            *(float4*)&sW1[o * P + h4 * 4] = g1[q];
            *(float4*)&sW2[o * P + h4 * 4] = g2[q];
        }
        for (int q = tid; q < H * NIN; q += TPB) {
            sW11[q] = w11[q];
            sW21[q] = w21[q];
        }
        if (tid < H) {
            sB11[tid] = b11[tid];
            sB21[tid] = b21[tid];
            sB12[tid] = b12[tid];
            sB22[tid] = b22[tid];
            sWout[tid] = wout[tid];
        }
        size_t base = (size_t)blockIdx.x * BT * NIN;
        for (int q = tid; q < BT * NIN; q += TPB) {
            int b = q >> 3, i = q & 7;
            sXt[i * BT + b] = x[base + q];
            if (GRAD) sXd[i * BT + b] = xdot[base + q];
        }
    }
    __syncthreads();

    // ---- Stage B: layer 1 (SKIP layer) -> sY (and tangent -> sDY) ----
    {
        int b  = tid & 63;
        int hg = tid >> 6;   // 0..3, covers 32 h each
        float xv[NIN], xd[NIN];
        #pragma unroll
        for (int i = 0; i < NIN; i++) {
            xv[i] = sXt[i * BT + b];
            if (GRAD) xd[i] = sXd[i * BT + b];
        }
        for (int hh = 0; hh < 32; hh++) {
            int h = hg * 32 + hh;
            float z1 = sB11[h], z2 = sB21[h];
            float d1 = 0.f, d2 = 0.f;
            #pragma unroll
            for (int i = 0; i < NIN; i++) {
                float a = sW11[h * NIN + i];
                float c = sW21[h * NIN + i];
                z1 = fmaf(xv[i], a, z1);
                z2 = fmaf(xv[i], c, z2);
                if (GRAD) {
                    d1 = fmaf(xd[i], a, d1);
                    d2 = fmaf(xd[i], c, d2);
                }
            }
            sY[b * P + h] = z1 * z2;
            if (GRAD) sDY[b * P + h] = fmaf(z1, d2, z2 * d1);
        }
    }
    __syncthreads();

    // ---- Stage C: layer 2 GEMMs (register-tiled, dot-product form) ----
    const int tx = tid & 15;   // output-neuron groups: o = tx + 16*j
    const int ty = tid >> 4;   // sample groups: b = ty + 16*i

    float acc1[4][8], acc2[4][8];
    float accd1[4][8], accd2[4][8];
    #pragma unroll
    for (int i = 0; i < 4; i++)
        #pragma unroll
        for (int j = 0; j < 8; j++) {
            acc1[i][j] = 0.f; acc2[i][j] = 0.f;
            if (GRAD) { accd1[i][j] = 0.f; accd2[i][j] = 0.f; }
        }

    for (int k = 0; k < H; k += 4) {
        float yf[4][4], dyf[4][4];
        #pragma unroll
        for (int i = 0; i < 4; i++) {
            float4 v = *(const float4*)&sY[(ty + 16 * i) * P + k];
            yf[i][0] = v.x; yf[i][1] = v.y; yf[i][2] = v.z; yf[i][3] = v.w;
            if (GRAD) {
                float4 d = *(const float4*)&sDY[(ty + 16 * i) * P + k];
                dyf[i][0] = d.x; dyf[i][1] = d.y; dyf[i][2] = d.z; dyf[i][3] = d.w;
            }
        }
        #pragma unroll
        for (int j = 0; j < 8; j++) {
            int o = tx + 16 * j;
            float4 w1v = *(const float4*)&sW1[o * P + k];
            float4 w2v = *(const float4*)&sW2[o * P + k];
            float w1f[4] = {w1v.x, w1v.y, w1v.z, w1v.w};
            float w2f[4] = {w2v.x, w2v.y, w2v.z, w2v.w};
            #pragma unroll
            for (int i = 0; i < 4; i++) {
                #pragma unroll
                for (int kk = 0; kk < 4; kk++) {
                    acc1[i][j] = fmaf(yf[i][kk], w1f[kk], acc1[i][j]);
                    acc2[i][j] = fmaf(yf[i][kk], w2f[kk], acc2[i][j]);
                    if (GRAD) {
                        accd1[i][j] = fmaf(dyf[i][kk], w1f[kk], accd1[i][j]);
                        accd2[i][j] = fmaf(dyf[i][kk], w2f[kk], accd2[i][j]);
                    }
                }
            }
        }
    }

    // ---- Epilogue: bias, multiplicative gate, w_out contraction, reduce over tx ----
    float resv[4], resg[4];
    #pragma unroll
    for (int i = 0; i < 4; i++) {
        float pv = 0.f, pg = 0.f;
        #pragma unroll
        for (int j = 0; j < 8; j++) {
            int o = tx + 16 * j;
            float u1 = acc1[i][j] + sB12[o];
            float u2 = acc2[i][j] + sB22[o];
            float wo = sWout[o];
            pv = fmaf(wo, u1 * u2, pv);
            if (GRAD)
                pg = fmaf(wo, fmaf(u1, accd2[i][j], u2 * accd1[i][j]), pg);
        }
        #pragma unroll
        for (int off = 8; off >= 1; off >>= 1) {
            pv += __shfl_xor_sync(0xffffffff, pv, off);
            if (GRAD) pg += __shfl_xor_sync(0xffffffff, pg, off);
        }
        resv[i] = pv;
        resg[i] = pg;
    }
    if (tx == 0) {
        #pragma unroll
        for (int i = 0; i < 4; i++) {
            int s = blockIdx.x * BT + ty + 16 * i;
            out_v[s] = resv[i];
            if (GRAD) out_g[s] = resg[i];
        }
    }
}

extern "C" void kernel_launch(void* const* d_in, const int* in_sizes, int n_in,
                              void* d_out, int out_size)
{
    const float* T      = (const float*)d_in[0];
    const float* l      = (const float*)d_in[1];
    const float* l1_dot = (const float*)d_in[2];
    const float* center = (const float*)d_in[3];
    const float* w11 = (const float*)d_in[4];
    const float* b11 = (const float*)d_in[5];
    const float* w21 = (const float*)d_in[6];
    const float* b21 = (const float*)d_in[7];
    const float* w12 = (const float*)d_in[8];
    const float* b12 = (const float*)d_in[9];
    const float* w22 = (const float*)d_in[10];
    const float* b22 = (const float*)d_in[11];
    const float* wout = (const float*)d_in[12];
    float* out = (float*)d_out;

    int nT = in_sizes[0] / NIN;   // 65536
    int nL = in_sizes[1] / NIN;   // 65536
    int nC = in_sizes[3] / NIN;   // 512

    cudaFuncSetAttribute(net_kernel<false>,
                         cudaFuncAttributeMaxDynamicSharedMemorySize, FWD_SMEM_B);
    cudaFuncSetAttribute(net_kernel<true>,
                         cudaFuncAttributeMaxDynamicSharedMemorySize, GRAD_SMEM_B);

    // out layout: [v_t (nT)] [v_y (nL)] [v_grad (nL)] [v_center (nC)]
    float* out_vt = out;
    float* out_vy = out + nT;
    float* out_vg = out + nT + nL;
    float* out_vc = out + nT + 2 * nL;

    net_kernel<false><<<nT / BT, TPB, FWD_SMEM_B>>>(
        T, nullptr, w11, b11, w21, b21, w12, b12, w22, b22, wout,
        out_vt, nullptr);
    net_kernel<true><<<nL / BT, TPB, GRAD_SMEM_B>>>(
        l, l1_dot, w11, b11, w21, b21, w12, b12, w22, b22, wout,
        out_vy, out_vg);
    net_kernel<false><<<nC / BT, TPB, FWD_SMEM_B>>>(
        center, nullptr, w11, b11, w21, b21, w12, b12, w22, b22, wout,
        out_vc, nullptr);
}

// round 2
// speedup vs baseline: 1.0014x; 1.0014x over previous
#include <cuda_runtime.h>

#define NIN 8
#define H   128
#define BT  64     // samples per block
#define P   132    // padded row stride (floats), multiple of 4, stride mod 32 = 4
#define TPB 256

// smem sizes in floats
#define FWD_SMEM_F  (2*H*P + BT*P + BT*NIN + 2*H*NIN + 5*H)
#define GRAD_SMEM_F (FWD_SMEM_F + BT*P + BT*NIN)
#define FWD_SMEM_B  (FWD_SMEM_F * 4)
#define GRAD_SMEM_B (GRAD_SMEM_F * 4)

template <bool GRAD>
__global__ __launch_bounds__(TPB)
void net_kernel(const float* __restrict__ x,     // (n, 8)
                const float* __restrict__ xdot,  // (n, 8) or null
                const float* __restrict__ w11, const float* __restrict__ b11,
                const float* __restrict__ w21, const float* __restrict__ b21,
                const float* __restrict__ w12, const float* __restrict__ b12,
                const float* __restrict__ w22, const float* __restrict__ b22,
                const float* __restrict__ wout,
                float* __restrict__ out_v,
                float* __restrict__ out_g)
{
    extern __shared__ float sm[];
    float* sW1 = sm;            // [H][P]   w1_2, row o, cols h
    float* sW2 = sW1 + H * P;   // [H][P]   w2_2
    float* sY  = sW2 + H * P;   // [BT][P]  hidden y, row b, cols h
    float* p   = sY + BT * P;
    float* sDY = p;             // [BT][P] (GRAD only)
    if (GRAD) p += BT * P;
    float* sXt = p; p += BT * NIN;     // [NIN][BT] transposed x tile
    float* sXd = p; if (GRAD) p += BT * NIN;
    float* sW11 = p; p += H * NIN;
    float* sW21 = p; p += H * NIN;
    float* sB11 = p; p += H;
    float* sB21 = p; p += H;
    float* sB12 = p; p += H;
    float* sB22 = p; p += H;
    float* sWout = p;

    const int tid = threadIdx.x;

    // ---- Stage A: load weights & inputs into smem ----
    {
        const float4* g1 = (const float4*)w12;
        const float4* g2 = (const float4*)w22;
        #pragma unroll
        for (int it = 0; it < (H * H / 4) / TPB; it++) {
            int q = tid + it * TPB;           // q in [0, 4096)
            int o  = q >> 5;                  // q / 32
            int h4 = q & 31;
            *(float4*)&sW1[o * P + h4 * 4] = g1[q];
            *(float4*)&sW2[o * P + h4 * 4] = g2[q];
        }
        for (int q = tid; q < H * NIN; q += TPB) {
            sW11[q] = w11[q];
            sW21[q] = w21[q];
        }
        if (tid < H) {
            sB11[tid] = b11[tid];
            sB21[tid] = b21[tid];
            sB12[tid] = b12[tid];
            sB22[tid] = b22[tid];
            sWout[tid] = wout[tid];
        }
        size_t base = (size_t)blockIdx.x * BT * NIN;
        for (int q = tid; q < BT * NIN; q += TPB) {
            int b = q >> 3, i = q & 7;
            sXt[i * BT + b] = x[base + q];
            if (GRAD) sXd[i * BT + b] = xdot[base + q];
        }
    }
    __syncthreads();

    // ---- Stage B: layer 1 (SKIP layer) -> sY (and tangent -> sDY) ----
    {
        int b  = tid & 63;
        int hg = tid >> 6;   // 0..3, covers 32 h each
        float xv[NIN], xd[NIN];
        #pragma unroll
        for (int i = 0; i < NIN; i++) {
            xv[i] = sXt[i * BT + b];
            if (GRAD) xd[i] = sXd[i * BT + b];
        }
        for (int hh = 0; hh < 32; hh++) {
            int h = hg * 32 + hh;
            float z1 = sB11[h], z2 = sB21[h];
            float d1 = 0.f, d2 = 0.f;
            #pragma unroll
            for (int i = 0; i < NIN; i++) {
                float a = sW11[h * NIN + i];
                float c = sW21[h * NIN + i];
                z1 = fmaf(xv[i], a, z1);
                z2 = fmaf(xv[i], c, z2);
                if (GRAD) {
                    d1 = fmaf(xd[i], a, d1);
                    d2 = fmaf(xd[i], c, d2);
                }
            }
            sY[b * P + h] = z1 * z2;
            if (GRAD) sDY[b * P + h] = fmaf(z1, d2, z2 * d1);
        }
    }
    __syncthreads();

    // ---- Stage C: layer 2 GEMMs (register-tiled, dot-product form) ----
    const int tx = tid & 15;   // output-neuron groups: o = tx + 16*j
    const int ty = tid >> 4;   // sample groups: b = ty + 16*i

    float acc1[4][8], acc2[4][8];
    float accd1[4][8], accd2[4][8];
    #pragma unroll
    for (int i = 0; i < 4; i++)
        #pragma unroll
        for (int j = 0; j < 8; j++) {
            acc1[i][j] = 0.f; acc2[i][j] = 0.f;
            if (GRAD) { accd1[i][j] = 0.f; accd2[i][j] = 0.f; }
        }

    for (int k = 0; k < H; k += 4) {
        float yf[4][4], dyf[4][4];
        #pragma unroll
        for (int i = 0; i < 4; i++) {
            float4 v = *(const float4*)&sY[(ty + 16 * i) * P + k];
            yf[i][0] = v.x; yf[i][1] = v.y; yf[i][2] = v.z; yf[i][3] = v.w;
            if (GRAD) {
                float4 d = *(const float4*)&sDY[(ty + 16 * i) * P + k];
                dyf[i][0] = d.x; dyf[i][1] = d.y; dyf[i][2] = d.z; dyf[i][3] = d.w;
            }
        }
        #pragma unroll
        for (int j = 0; j < 8; j++) {
            int o = tx + 16 * j;
            float4 w1v = *(const float4*)&sW1[o * P + k];
            float4 w2v = *(const float4*)&sW2[o * P + k];
            float w1f[4] = {w1v.x, w1v.y, w1v.z, w1v.w};
            float w2f[4] = {w2v.x, w2v.y, w2v.z, w2v.w};
            #pragma unroll
            for (int i = 0; i < 4; i++) {
                #pragma unroll
                for (int kk = 0; kk < 4; kk++) {
                    acc1[i][j] = fmaf(yf[i][kk], w1f[kk], acc1[i][j]);
                    acc2[i][j] = fmaf(yf[i][kk], w2f[kk], acc2[i][j]);
                    if (GRAD) {
                        accd1[i][j] = fmaf(dyf[i][kk], w1f[kk], accd1[i][j]);
                        accd2[i][j] = fmaf(dyf[i][kk], w2f[kk], accd2[i][j]);
                    }
                }
            }
        }
    }

    // ---- Epilogue: bias, multiplicative gate, w_out contraction, reduce over tx ----
    float resv[4], resg[4];
    #pragma unroll
    for (int i = 0; i < 4; i++) {
        float pv = 0.f, pg = 0.f;
        #pragma unroll
        for (int j = 0; j < 8; j++) {
            int o = tx + 16 * j;
            float u1 = acc1[i][j] + sB12[o];
            float u2 = acc2[i][j] + sB22[o];
            float wo = sWout[o];
            pv = fmaf(wo, u1 * u2, pv);
            if (GRAD)
                pg = fmaf(wo, fmaf(u1, accd2[i][j], u2 * accd1[i][j]), pg);
        }
        #pragma unroll
        for (int off = 8; off >= 1; off >>= 1) {
            pv += __shfl_xor_sync(0xffffffff, pv, off);
            if (GRAD) pg += __shfl_xor_sync(0xffffffff, pg, off);
        }
        resv[i] = pv;
        resg[i] = pg;
    }
    if (tx == 0) {
        #pragma unroll
        for (int i = 0; i < 4; i++) {
            int s = blockIdx.x * BT + ty + 16 * i;
            out_v[s] = resv[i];
            if (GRAD) out_g[s] = resg[i];
        }
    }
}

extern "C" void kernel_launch(void* const* d_in, const int* in_sizes, int n_in,
                              void* d_out, int out_size)
{
    const float* T      = (const float*)d_in[0];
    const float* l      = (const float*)d_in[1];
    const float* l1_dot = (const float*)d_in[2];
    const float* center = (const float*)d_in[3];
    const float* w11 = (const float*)d_in[4];
    const float* b11 = (const float*)d_in[5];
    const float* w21 = (const float*)d_in[6];
    const float* b21 = (const float*)d_in[7];
    const float* w12 = (const float*)d_in[8];
    const float* b12 = (const float*)d_in[9];
    const float* w22 = (const float*)d_in[10];
    const float* b22 = (const float*)d_in[11];
    const float* wout = (const float*)d_in[12];
    float* out = (float*)d_out;

    int nT = in_sizes[0] / NIN;   // 65536
    int nL = in_sizes[1] / NIN;   // 65536
    int nC = in_sizes[3] / NIN;   // 512

    cudaFuncSetAttribute(net_kernel<false>,
                         cudaFuncAttributeMaxDynamicSharedMemorySize, FWD_SMEM_B);
    cudaFuncSetAttribute(net_kernel<true>,
                         cudaFuncAttributeMaxDynamicSharedMemorySize, GRAD_SMEM_B);

    // out layout: [v_t (nT)] [v_y (nL)] [v_grad (nL)] [v_center (nC)]
    float* out_vt = out;
    float* out_vy = out + nT;
    float* out_vg = out + nT + nL;
    float* out_vc = out + nT + 2 * nL;

    net_kernel<false><<<nT / BT, TPB, FWD_SMEM_B>>>(
        T, nullptr, w11, b11, w21, b21, w12, b12, w22, b22, wout,
        out_vt, nullptr);
    net_kernel<true><<<nL / BT, TPB, GRAD_SMEM_B>>>(
        l, l1_dot, w11, b11, w21, b21, w12, b12, w22, b22, wout,
        out_vy, out_vg);
    net_kernel<false><<<nC / BT, TPB, FWD_SMEM_B>>>(
        center, nullptr, w11, b11, w21, b21, w12, b12, w22, b22, wout,
        out_vc, nullptr);
}

// round 5
// speedup vs baseline: 2.0742x; 2.0713x over previous
#include <cuda_runtime.h>
#include <cuda_bf16.h>
#include <cstdint>

#define TPB 256

__device__ __forceinline__ uint32_t smem_u32(const void* p) {
    uint32_t a;
    asm("{ .reg .u64 t; cvta.to.shared.u64 t, %1; cvt.u32.u64 %0, t; }" : "=r"(a) : "l"(p));
    return a;
}

#define LDSM4(r, addr) \
    asm volatile("ldmatrix.sync.aligned.m8n8.x4.shared.b16 {%0,%1,%2,%3}, [%4];" \
        : "=r"((r)[0]), "=r"((r)[1]), "=r"((r)[2]), "=r"((r)[3]) : "r"(addr))

#define MMA(c, a, b) \
    asm volatile("mma.sync.aligned.m16n8k16.row.col.f32.bf16.bf16.f32 " \
        "{%0,%1,%2,%3}, {%4,%5,%6,%7}, {%8,%9}, {%0,%1,%2,%3};" \
        : "+f"((c)[0]), "+f"((c)[1]), "+f"((c)[2]), "+f"((c)[3]) \
        : "r"((a)[0]), "r"((a)[1]), "r"((a)[2]), "r"((a)[3]), "r"((b)[0]), "r"((b)[1]))

// swizzled byte offset of bf16 element (row, col) in a [rows x 128] tile (256B/row):
// 16B chunks XOR'd with (row & 7) for conflict-free ldmatrix.
__device__ __forceinline__ uint32_t swz(int row, int col) {
    return (uint32_t)(row * 256 + ((((col >> 3) ^ (row & 7)) & 15) << 4) + (col & 7) * 2);
}

// ---------------- prep: split W1/W2 into bf16 hi/lo swizzled images ----------------
__device__ uint32_t gBimg[4][8192];   // [W1h, W1l, W2h, W2l], each 128x128 bf16 = 32KB

__global__ void prep_kernel(const float* __restrict__ w12, const float* __restrict__ w22) {
    int m = blockIdx.x;
    const float* src = (m < 2) ? w12 : w22;
    int lo = m & 1;
    for (int idx = threadIdx.x; idx < 8192; idx += blockDim.x) {
        int o = idx >> 6, c = (idx & 63) * 2;
        float a = src[o * 128 + c], b = src[o * 128 + c + 1];
        __nv_bfloat16 ah = __float2bfloat16_rn(a);
        __nv_bfloat16 bh = __float2bfloat16_rn(b);
        __nv_bfloat16 v0, v1;
        if (lo) {
            v0 = __float2bfloat16_rn(a - __bfloat162float(ah));
            v1 = __float2bfloat16_rn(b - __bfloat162float(bh));
        } else { v0 = ah; v1 = bh; }
        uint32_t pack = (uint32_t)__bfloat16_as_ushort(v0) |
                        ((uint32_t)__bfloat16_as_ushort(v1) << 16);
        gBimg[m][swz(o, c) >> 2] = pack;
    }
}

// ---------------- smem layout (bytes) ----------------
#define SM_W     0          // 4 x 32768 = 131072
#define SM_A     131072     // 65536 (grad: 4 imgs x 16KB; fwd: 2 imgs x 32KB)
#define SM_STAGE 196608     // 4KB
#define SM_W11   200704     // 4KB
#define SM_W21   204800     // 4KB
#define SM_CONST 208896     // b11,b21,b12,b22,wout: 5 x 512
#define SM_RED   211456     // 4KB reduction scratch
#define SM_TOTAL 215552

template <bool GRAD>
__global__ __launch_bounds__(TPB, 1)
void net3(const float* __restrict__ x, const float* __restrict__ xdot,
          const float* __restrict__ w11, const float* __restrict__ b11,
          const float* __restrict__ b21g, const float* __restrict__ w21,
          const float* __restrict__ b12g, const float* __restrict__ b22g,
          const float* __restrict__ wout,
          float* __restrict__ out_v, float* __restrict__ out_g, int ntiles)
{
    extern __shared__ char smem[];
    const uint32_t sb = smem_u32(smem);
    const int tid = threadIdx.x;
    const int wid = tid >> 5, lane = tid & 31;

    float* sStage = (float*)(smem + SM_STAGE);
    float* sW11 = (float*)(smem + SM_W11);
    float* sW21 = (float*)(smem + SM_W21);
    float* sB11 = (float*)(smem + SM_CONST);
    float* sB21 = sB11 + 128;
    float* sB12 = sB21 + 128;
    float* sB22 = sB12 + 128;
    float* sWo  = sB22 + 128;
    float* sRedV = (float*)(smem + SM_RED);            // [SPT][8]
    float* sRedG = sRedV + (GRAD ? 512 : 0);           // [64][8] grad only

    // resident loads
    {
        const float4* gb = (const float4*)gBimg;
        float4* sbv = (float4*)(smem + SM_W);
        for (int i = tid; i < 8192; i += TPB) sbv[i] = gb[i];
        for (int i = tid; i < 1024; i += TPB) { sW11[i] = w11[i]; sW21[i] = w21[i]; }
        if (tid < 128) {
            sB11[tid] = b11[tid]; sB21[tid] = b21g[tid];
            sB12[tid] = b12g[tid]; sB22[tid] = b22g[tid]; sWo[tid] = wout[tid];
        }
    }

    constexpr int SPT  = GRAD ? 64 : 128;   // samples per tile
    constexpr int NMT  = GRAD ? 4 : 8;      // 16-row m-tiles
    constexpr int AIMG = GRAD ? 16384 : 32768;
    const int s  = tid & (SPT - 1);
    const int hc = tid / SPT;
    constexpr int HPT = 128 / (TPB / SPT);  // 32 (grad) / 64 (fwd)
    const int n0 = wid * 16;

    // per-thread output-column constants for the epilogue
    const int g4 = lane >> 2, q4 = lane & 3;
    float B12v[2][2], B22v[2][2], WOv[2][2];

    __syncthreads();
    #pragma unroll
    for (int nt = 0; nt < 2; nt++)
        #pragma unroll
        for (int e = 0; e < 2; e++) {
            int c = n0 + nt * 8 + q4 * 2 + e;
            B12v[nt][e] = sB12[c]; B22v[nt][e] = sB22[c]; WOv[nt][e] = sWo[c];
        }

    for (int tile = blockIdx.x; tile < ntiles; tile += gridDim.x) {
        __syncthreads();
        // ---- stage x (and xd) ----
        if (!GRAD) {
            if (tid < 128) {
                const float4* g = (const float4*)(x + (size_t)(tile * 128 + tid) * 8);
                ((float4*)sStage)[tid * 2] = g[0];
                ((float4*)sStage)[tid * 2 + 1] = g[1];
            }
        } else {
            if (tid < 64) {
                const float4* g = (const float4*)(x + (size_t)(tile * 64 + tid) * 8);
                ((float4*)sStage)[tid * 2] = g[0];
                ((float4*)sStage)[tid * 2 + 1] = g[1];
            } else if (tid < 128) {
                int t = tid - 64;
                const float4* g = (const float4*)(xdot + (size_t)(tile * 64 + t) * 8);
                ((float4*)sStage)[128 + t * 2] = g[0];
                ((float4*)sStage)[128 + t * 2 + 1] = g[1];
            }
        }
        __syncthreads();

        // ---- layer 1 (scalar) -> swizzled bf16 hi/lo A-images ----
        {
            float xv[8], xd[8];
            #pragma unroll
            for (int i = 0; i < 8; i++) {
                xv[i] = sStage[s * 8 + i];
                if (GRAD) xd[i] = sStage[512 + s * 8 + i];
            }
            #pragma unroll 4
            for (int jp = 0; jp < HPT / 2; jp++) {
                float yy[2], dd[2];
                #pragma unroll
                for (int q = 0; q < 2; q++) {
                    int h = hc * HPT + jp * 2 + q;
                    float z1 = sB11[h], z2 = sB21[h], d1 = 0.f, d2 = 0.f;
                    #pragma unroll
                    for (int i = 0; i < 8; i++) {
                        float a = sW11[h * 8 + i], c = sW21[h * 8 + i];
                        z1 = fmaf(xv[i], a, z1);
                        z2 = fmaf(xv[i], c, z2);
                        if (GRAD) { d1 = fmaf(xd[i], a, d1); d2 = fmaf(xd[i], c, d2); }
                    }
                    yy[q] = z1 * z2;
                    if (GRAD) dd[q] = fmaf(z1, d2, z2 * d1);
                }
                int c0 = hc * HPT + jp * 2;
                uint32_t off = swz(s, c0);
                __nv_bfloat16 h0 = __float2bfloat16_rn(yy[0]);
                __nv_bfloat16 h1 = __float2bfloat16_rn(yy[1]);
                uint32_t ph = (uint32_t)__bfloat16_as_ushort(h0) |
                              ((uint32_t)__bfloat16_as_ushort(h1) << 16);
                __nv_bfloat16 l0 = __float2bfloat16_rn(yy[0] - __bfloat162float(h0));
                __nv_bfloat16 l1 = __float2bfloat16_rn(yy[1] - __bfloat162float(h1));
                uint32_t pl = (uint32_t)__bfloat16_as_ushort(l0) |
                              ((uint32_t)__bfloat16_as_ushort(l1) << 16);
                *(uint32_t*)(smem + SM_A + off) = ph;
                *(uint32_t*)(smem + SM_A + AIMG + off) = pl;
                if (GRAD) {
                    __nv_bfloat16 g0 = __float2bfloat16_rn(dd[0]);
                    __nv_bfloat16 g1 = __float2bfloat16_rn(dd[1]);
                    uint32_t pd = (uint32_t)__bfloat16_as_ushort(g0) |
                                  ((uint32_t)__bfloat16_as_ushort(g1) << 16);
                    __nv_bfloat16 e0 = __float2bfloat16_rn(dd[0] - __bfloat162float(g0));
                    __nv_bfloat16 e1 = __float2bfloat16_rn(dd[1] - __bfloat162float(g1));
                    uint32_t pe = (uint32_t)__bfloat16_as_ushort(e0) |
                                  ((uint32_t)__bfloat16_as_ushort(e1) << 16);
                    *(uint32_t*)(smem + SM_A + 2 * AIMG + off) = pd;
                    *(uint32_t*)(smem + SM_A + 3 * AIMG + off) = pe;
                }
            }
        }
        __syncthreads();

        // ---- layer 2: bf16 3-term split mma.sync ----
        float cz1[NMT][2][4], cz2[NMT][2][4];
        float cd1[GRAD ? NMT : 1][2][4], cd2[GRAD ? NMT : 1][2][4];
        #pragma unroll
        for (int mt = 0; mt < NMT; mt++)
            #pragma unroll
            for (int nt = 0; nt < 2; nt++)
                #pragma unroll
                for (int e = 0; e < 4; e++) {
                    cz1[mt][nt][e] = 0.f; cz2[mt][nt][e] = 0.f;
                    if (GRAD) { cd1[mt][nt][e] = 0.f; cd2[mt][nt][e] = 0.f; }
                }

        #pragma unroll 1
        for (int kt = 0; kt < 8; kt++) {
            const int k0 = kt * 16;
            uint32_t bf[4][4];
            {
                int nrow = n0 + (lane & 7) + ((lane >> 4) << 3);
                int kc = k0 + ((lane >> 3) & 1) * 8;
                uint32_t off = swz(nrow, kc);
                #pragma unroll
                for (int img = 0; img < 4; img++)
                    LDSM4(bf[img], sb + SM_W + img * 32768 + off);
            }
            #pragma unroll
            for (int mt = 0; mt < NMT; mt++) {
                int row = mt * 16 + (lane & 7) + ((lane >> 3) & 1) * 8;
                int kc = k0 + (lane >> 4) * 8;
                uint32_t off = swz(row, kc);
                uint32_t aYh[4], aYl[4], aDh[4], aDl[4];
                LDSM4(aYh, sb + SM_A + off);
                LDSM4(aYl, sb + SM_A + AIMG + off);
                if (GRAD) {
                    LDSM4(aDh, sb + SM_A + 2 * AIMG + off);
                    LDSM4(aDl, sb + SM_A + 3 * AIMG + off);
                }
                #pragma unroll
                for (int nt = 0; nt < 2; nt++) {
                    MMA(cz1[mt][nt], aYh, (&bf[0][nt * 2]));
                    MMA(cz1[mt][nt], aYh, (&bf[1][nt * 2]));
                    MMA(cz1[mt][nt], aYl, (&bf[0][nt * 2]));
                    MMA(cz2[mt][nt], aYh, (&bf[2][nt * 2]));
                    MMA(cz2[mt][nt], aYh, (&bf[3][nt * 2]));
                    MMA(cz2[mt][nt], aYl, (&bf[2][nt * 2]));
                    if (GRAD) {
                        MMA(cd1[mt][nt], aDh, (&bf[0][nt * 2]));
                        MMA(cd1[mt][nt], aDh, (&bf[1][nt * 2]));
                        MMA(cd1[mt][nt], aDl, (&bf[0][nt * 2]));
                        MMA(cd2[mt][nt], aDh, (&bf[2][nt * 2]));
                        MMA(cd2[mt][nt], aDh, (&bf[3][nt * 2]));
                        MMA(cd2[mt][nt], aDl, (&bf[2][nt * 2]));
                    }
                }
            }
        }

        // ---- epilogue: gate + w_out contraction from register C frags ----
        #pragma unroll
        for (int mt = 0; mt < NMT; mt++) {
            float pv0 = 0.f, pv1 = 0.f, pg0 = 0.f, pg1 = 0.f;
            #pragma unroll
            for (int nt = 0; nt < 2; nt++) {
                float u1a = cz1[mt][nt][0] + B12v[nt][0];
                float u1b = cz1[mt][nt][1] + B12v[nt][1];
                float u1c = cz1[mt][nt][2] + B12v[nt][0];
                float u1d = cz1[mt][nt][3] + B12v[nt][1];
                float u2a = cz2[mt][nt][0] + B22v[nt][0];
                float u2b = cz2[mt][nt][1] + B22v[nt][1];
                float u2c = cz2[mt][nt][2] + B22v[nt][0];
                float u2d = cz2[mt][nt][3] + B22v[nt][1];
                pv0 = fmaf(WOv[nt][0], u1a * u2a, pv0);
                pv0 = fmaf(WOv[nt][1], u1b * u2b, pv0);
                pv1 = fmaf(WOv[nt][0], u1c * u2c, pv1);
                pv1 = fmaf(WOv[nt][1], u1d * u2d, pv1);
                if (GRAD) {
                    pg0 = fmaf(WOv[nt][0], fmaf(u1a, cd2[mt][nt][0], u2a * cd1[mt][nt][0]), pg0);
                    pg0 = fmaf(WOv[nt][1], fmaf(u1b, cd2[mt][nt][1], u2b * cd1[mt][nt][1]), pg0);
                    pg1 = fmaf(WOv[nt][0], fmaf(u1c, cd2[mt][nt][2], u2c * cd1[mt][nt][2]), pg1);
                    pg1 = fmaf(WOv[nt][1], fmaf(u1d, cd2[mt][nt][3], u2d * cd1[mt][nt][3]), pg1);
                }
            }
            pv0 += __shfl_xor_sync(0xffffffff, pv0, 1);
            pv0 += __shfl_xor_sync(0xffffffff, pv0, 2);
            pv1 += __shfl_xor_sync(0xffffffff, pv1, 1);
            pv1 += __shfl_xor_sync(0xffffffff, pv1, 2);
            if (GRAD) {
                pg0 += __shfl_xor_sync(0xffffffff, pg0, 1);
                pg0 += __shfl_xor_sync(0xffffffff, pg0, 2);
                pg1 += __shfl_xor_sync(0xffffffff, pg1, 1);
                pg1 += __shfl_xor_sync(0xffffffff, pg1, 2);
            }
            if (q4 == 0) {
                int r0 = mt * 16 + g4, r1 = r0 + 8;
                sRedV[r0 * 8 + wid] = pv0;
                sRedV[r1 * 8 + wid] = pv1;
                if (GRAD) { sRedG[r0 * 8 + wid] = pg0; sRedG[r1 * 8 + wid] = pg1; }
            }
        }
        __syncthreads();

        if (!GRAD) {
            if (tid < 128) {
                float v = 0.f;
                #pragma unroll
                for (int w = 0; w < 8; w++) v += sRedV[tid * 8 + w];
                out_v[(size_t)tile * 128 + tid] = v;
            }
        } else {
            if (tid < 64) {
                float v = 0.f;
                #pragma unroll
                for (int w = 0; w < 8; w++) v += sRedV[tid * 8 + w];
                out_v[(size_t)tile * 64 + tid] = v;
            } else if (tid < 128) {
                int r = tid - 64;
                float g = 0.f;
                #pragma unroll
                for (int w = 0; w < 8; w++) g += sRedG[r * 8 + w];
                out_g[(size_t)tile * 64 + r] = g;
            }
        }
    }
}

extern "C" void kernel_launch(void* const* d_in, const int* in_sizes, int n_in,
                              void* d_out, int out_size)
{
    const float* T      = (const float*)d_in[0];
    const float* l      = (const float*)d_in[1];
    const float* l1_dot = (const float*)d_in[2];
    const float* center = (const float*)d_in[3];
    const float* w11 = (const float*)d_in[4];
    const float* b11 = (const float*)d_in[5];
    const float* w21 = (const float*)d_in[6];
    const float* b21 = (const float*)d_in[7];
    const float* w12 = (const float*)d_in[8];
    const float* b12 = (const float*)d_in[9];
    const float* w22 = (const float*)d_in[10];
    const float* b22 = (const float*)d_in[11];
    const float* wout = (const float*)d_in[12];
    float* out = (float*)d_out;

    int nT = in_sizes[0] / 8;   // 65536
    int nL = in_sizes[1] / 8;   // 65536
    int nC = in_sizes[3] / 8;   // 512

    cudaFuncSetAttribute(net3<false>, cudaFuncAttributeMaxDynamicSharedMemorySize, SM_TOTAL);
    cudaFuncSetAttribute(net3<true>,  cudaFuncAttributeMaxDynamicSharedMemorySize, SM_TOTAL);

    float* out_vt = out;
    float* out_vy = out + nT;
    float* out_vg = out + nT + nL;
    float* out_vc = out + nT + 2 * nL;

    prep_kernel<<<4, 256>>>(w12, w22);
    net3<false><<<148, TPB, SM_TOTAL>>>(T, nullptr, w11, b11, b21, w21, b12, b22, wout,
                                        out_vt, nullptr, nT / 128);
    net3<true><<<148, TPB, SM_TOTAL>>>(l, l1_dot, w11, b11, b21, w21, b12, b22, wout,
                                       out_vy, out_vg, nL / 64);
    net3<false><<<4, TPB, SM_TOTAL>>>(center, nullptr, w11, b11, b21, w21, b12, b22, wout,
                                      out_vc, nullptr, nC / 128);
}

// round 9
// speedup vs baseline: 2.8514x; 1.3747x over previous
#include <cuda_runtime.h>
#include <cuda_bf16.h>
#include <cstdint>

#define TPB 256

__device__ __forceinline__ uint32_t smem_u32(const void* p) {
    uint32_t a;
    asm("{ .reg .u64 t; cvta.to.shared.u64 t, %1; cvt.u32.u64 %0, t; }" : "=r"(a) : "l"(p));
    return a;
}

#define LDSM4(r, addr) \
    asm volatile("ldmatrix.sync.aligned.m8n8.x4.shared.b16 {%0,%1,%2,%3}, [%4];" \
        : "=r"((r)[0]), "=r"((r)[1]), "=r"((r)[2]), "=r"((r)[3]) : "r"(addr))
#define LDSM2(r, addr) \
    asm volatile("ldmatrix.sync.aligned.m8n8.x2.shared.b16 {%0,%1}, [%2];" \
        : "=r"((r)[0]), "=r"((r)[1]) : "r"(addr))

#define MMA16(c, a, b) \
    asm volatile("mma.sync.aligned.m16n8k16.row.col.f32.bf16.bf16.f32 " \
        "{%0,%1,%2,%3}, {%4,%5,%6,%7}, {%8,%9}, {%0,%1,%2,%3};" \
        : "+f"((c)[0]), "+f"((c)[1]), "+f"((c)[2]), "+f"((c)[3]) \
        : "r"((a)[0]), "r"((a)[1]), "r"((a)[2]), "r"((a)[3]), "r"((b)[0]), "r"((b)[1]))
#define MMA8(c, a, b) \
    asm volatile("mma.sync.aligned.m16n8k8.row.col.f32.bf16.bf16.f32 " \
        "{%0,%1,%2,%3}, {%4,%5}, {%6}, {%0,%1,%2,%3};" \
        : "+f"((c)[0]), "+f"((c)[1]), "+f"((c)[2]), "+f"((c)[3]) \
        : "r"((a)[0]), "r"((a)[1]), "r"(b))

// swizzled byte offset in a [rows x 128] bf16 tile, 256B rows, 16B-chunk XOR swizzle
__device__ __forceinline__ uint32_t swz(int row, int col) {
    return (uint32_t)(row * 256 + ((((col >> 3) ^ (row & 7)) & 15) << 4) + (col & 7) * 2);
}

// split a,b into bf16 hi-pair (return) and lo-pair (out param)
__device__ __forceinline__ uint32_t packsplit(float a, float b, uint32_t& lo) {
    __nv_bfloat16 ah = __float2bfloat16_rn(a), bh = __float2bfloat16_rn(b);
    __nv_bfloat16 al = __float2bfloat16_rn(a - __bfloat162float(ah));
    __nv_bfloat16 bl = __float2bfloat16_rn(b - __bfloat162float(bh));
    lo = (uint32_t)__bfloat16_as_ushort(al) | ((uint32_t)__bfloat16_as_ushort(bl) << 16);
    return (uint32_t)__bfloat16_as_ushort(ah) | ((uint32_t)__bfloat16_as_ushort(bh) << 16);
}

// ---------------- device scratch: prebuilt weight images ----------------
__device__ uint32_t gBimg[4][8192];   // layer-2: [W1h, W1l, W2h, W2l], 128x128 bf16, swz layout
__device__ uint32_t gW1img[4][512];   // layer-1: [W11h, W11l, W21h, W21l], 128x8 bf16, 16B rows

__global__ void prep_kernel(const float* __restrict__ w12, const float* __restrict__ w22,
                            const float* __restrict__ w11, const float* __restrict__ w21) {
    int m = blockIdx.x;
    if (m < 4) {
        const float* src = (m < 2) ? w12 : w22;
        int lo = m & 1;
        for (int idx = threadIdx.x; idx < 8192; idx += blockDim.x) {
            int o = idx >> 6, c = (idx & 63) * 2;
            float a = src[o * 128 + c], b = src[o * 128 + c + 1];
            uint32_t pl, ph = packsplit(a, b, pl);
            gBimg[m][swz(o, c) >> 2] = lo ? pl : ph;
        }
    } else {
        for (int idx = threadIdx.x; idx < 2048; idx += blockDim.x) {
            int img = idx >> 9, r = (idx >> 2) & 127, cp = idx & 3;
            const float* src = (img < 2) ? w11 : w21;
            float a = src[r * 8 + cp * 2], b = src[r * 8 + cp * 2 + 1];
            uint32_t pl, ph = packsplit(a, b, pl);
            gW1img[img][r * 4 + cp] = (img & 1) ? pl : ph;
        }
    }
}

// ---------------- smem layout (bytes) ----------------
#define SM_W     0          // layer-2 W images: 4 x 32768
#define SM_A     131072     // A images: 64KB (fwd 2x32KB, grad 4x16KB)
#define SM_X     196608     // X images: 4 x 2048
#define SM_W1    204800     // layer-1 W images: 4 x 2048
#define SM_CONST 212992     // b11,b21,b12,b22,wout: 5 x 512
#define SM_RED   215552     // 2048
#define SM_TOTAL 217600

template <bool GRAD>
__global__ __launch_bounds__(TPB, 1)
void net4(const float* __restrict__ xa, const float* __restrict__ xb,
          const float* __restrict__ xdot,
          const float* __restrict__ b11g, const float* __restrict__ b21g,
          const float* __restrict__ b12g, const float* __restrict__ b22g,
          const float* __restrict__ woutg,
          float* __restrict__ outa, float* __restrict__ outb,
          float* __restrict__ out_g,
          int ntiles, int na)
{
    extern __shared__ char smem[];
    const uint32_t sb = smem_u32(smem);
    const int tid = threadIdx.x;
    const int wid = tid >> 5, lane = tid & 31;
    const int g4 = lane >> 2, q4 = lane & 3;

    constexpr int SPT  = GRAD ? 64 : 128;   // samples per tile
    constexpr int MT   = GRAD ? 2 : 4;      // 16-row m-tiles per warp
    constexpr int AIMG = GRAD ? 16384 : 32768;

    const int wm = wid & 1, wn = wid >> 1;
    const int m0 = wm * (SPT / 2);
    const int n0 = wn * 32;

    float* sC   = (float*)(smem + SM_CONST);
    float* sRedV = (float*)(smem + SM_RED);
    float* sRedG = sRedV + 256;

    // resident loads
    {
        const float4* gb = (const float4*)gBimg;
        float4* sw = (float4*)(smem + SM_W);
        for (int i = tid; i < 8192; i += TPB) sw[i] = gb[i];
        const float4* g1 = (const float4*)gW1img;
        float4* sw1 = (float4*)(smem + SM_W1);
        for (int i = tid; i < 512; i += TPB) sw1[i] = g1[i];
        if (tid < 128) {
            sC[tid] = b11g[tid]; sC[128 + tid] = b21g[tid];
            sC[256 + tid] = b12g[tid]; sC[384 + tid] = b22g[tid];
            sC[512 + tid] = woutg[tid];
        }
    }
    __syncthreads();

    // hoisted per-thread column constants
    float B11c[4][2], B21c[4][2], B12v[4][2], B22v[4][2], WOv[4][2];
    #pragma unroll
    for (int j = 0; j < 4; j++)
        #pragma unroll
        for (int e = 0; e < 2; e++) {
            int c = n0 + j * 8 + q4 * 2 + e;
            B11c[j][e] = sC[c]; B21c[j][e] = sC[128 + c];
            B12v[j][e] = sC[256 + c]; B22v[j][e] = sC[384 + c];
            WOv[j][e] = sC[512 + c];
        }
    // hoisted layer-1 weight b-frags
    uint32_t w1f[4][4];
    #pragma unroll
    for (int img = 0; img < 4; img++)
        #pragma unroll
        for (int ng = 0; ng < 2; ng++)
            LDSM2(&w1f[img][ng * 2],
                  sb + SM_W1 + img * 2048 + (uint32_t)(n0 + ng * 16 + (lane & 15)) * 16);

    for (int tile = blockIdx.x; tile < ntiles; tile += gridDim.x) {
        __syncthreads();
        // ---- stage X images (bf16 hi/lo split) ----
        if (tid < 128) {
            const float* xp;
            uint32_t xoff;
            int t;
            if (!GRAD) {
                t = tid;
                xp = (tile < na) ? xa + (size_t)tile * (128 * 8)
                                 : xb + (size_t)(tile - na) * (128 * 8);
                xoff = 0;
            } else {
                t = tid & 63;
                xp = (tid < 64) ? xa + (size_t)tile * (64 * 8)
                                : xdot + (size_t)tile * (64 * 8);
                xoff = (tid < 64) ? 0 : 4096;
            }
            const float4* g = (const float4*)(xp + (size_t)t * 8);
            float4 v0 = g[0], v1 = g[1];
            float v[8] = {v0.x, v0.y, v0.z, v0.w, v1.x, v1.y, v1.z, v1.w};
            uint32_t hi[4], lo[4];
            #pragma unroll
            for (int i = 0; i < 4; i++) hi[i] = packsplit(v[2 * i], v[2 * i + 1], lo[i]);
            *(uint4*)(smem + SM_X + xoff + t * 16) = make_uint4(hi[0], hi[1], hi[2], hi[3]);
            *(uint4*)(smem + SM_X + xoff + 2048 + t * 16) = make_uint4(lo[0], lo[1], lo[2], lo[3]);
        }
        __syncthreads();

        // ---- layer 1 via m16n8k8 MMA ----
        {
            float z1[MT][4][4], z2[MT][4][4];
            float d1[GRAD ? MT : 1][4][4], d2[GRAD ? MT : 1][4][4];
            #pragma unroll
            for (int mt = 0; mt < MT; mt++)
                #pragma unroll
                for (int j = 0; j < 4; j++)
                    #pragma unroll
                    for (int e = 0; e < 4; e++) {
                        z1[mt][j][e] = 0.f; z2[mt][j][e] = 0.f;
                        if (GRAD) { d1[mt][j][e] = 0.f; d2[mt][j][e] = 0.f; }
                    }
            #pragma unroll
            for (int mt = 0; mt < MT; mt++) {
                uint32_t xh[2], xl[2], xdh[2], xdl[2];
                uint32_t xr = (uint32_t)(m0 + mt * 16 + (lane & 15)) * 16;
                LDSM2(xh, sb + SM_X + xr);
                LDSM2(xl, sb + SM_X + 2048 + xr);
                if (GRAD) {
                    LDSM2(xdh, sb + SM_X + 4096 + xr);
                    LDSM2(xdl, sb + SM_X + 6144 + xr);
                }
                #pragma unroll
                for (int j = 0; j < 4; j++) {
                    MMA8(z1[mt][j], xh, w1f[0][j]);
                    MMA8(z1[mt][j], xh, w1f[1][j]);
                    MMA8(z1[mt][j], xl, w1f[0][j]);
                    MMA8(z2[mt][j], xh, w1f[2][j]);
                    MMA8(z2[mt][j], xh, w1f[3][j]);
                    MMA8(z2[mt][j], xl, w1f[2][j]);
                    if (GRAD) {
                        MMA8(d1[mt][j], xdh, w1f[0][j]);
                        MMA8(d1[mt][j], xdh, w1f[1][j]);
                        MMA8(d1[mt][j], xdl, w1f[0][j]);
                        MMA8(d2[mt][j], xdh, w1f[2][j]);
                        MMA8(d2[mt][j], xdh, w1f[3][j]);
                        MMA8(d2[mt][j], xdl, w1f[2][j]);
                    }
                }
            }
            // gate + split + store A images
            #pragma unroll
            for (int mt = 0; mt < MT; mt++)
                #pragma unroll
                for (int j = 0; j < 4; j++) {
                    float u1[4], u2[4], y[4];
                    #pragma unroll
                    for (int e = 0; e < 4; e++) {
                        u1[e] = z1[mt][j][e] + B11c[j][e & 1];
                        u2[e] = z2[mt][j][e] + B21c[j][e & 1];
                        y[e] = u1[e] * u2[e];
                    }
                    int row = m0 + mt * 16 + g4;
                    int col = n0 + j * 8 + q4 * 2;
                    uint32_t o0 = swz(row, col), o1 = swz(row + 8, col);
                    uint32_t l01, h01 = packsplit(y[0], y[1], l01);
                    uint32_t l23, h23 = packsplit(y[2], y[3], l23);
                    *(uint32_t*)(smem + SM_A + o0) = h01;
                    *(uint32_t*)(smem + SM_A + AIMG + o0) = l01;
                    *(uint32_t*)(smem + SM_A + o1) = h23;
                    *(uint32_t*)(smem + SM_A + AIMG + o1) = l23;
                    if (GRAD) {
                        float dy[4];
                        #pragma unroll
                        for (int e = 0; e < 4; e++)
                            dy[e] = fmaf(u1[e], d2[mt][j][e], u2[e] * d1[mt][j][e]);
                        uint32_t dl01, dh01 = packsplit(dy[0], dy[1], dl01);
                        uint32_t dl23, dh23 = packsplit(dy[2], dy[3], dl23);
                        *(uint32_t*)(smem + SM_A + 2 * AIMG + o0) = dh01;
                        *(uint32_t*)(smem + SM_A + 3 * AIMG + o0) = dl01;
                        *(uint32_t*)(smem + SM_A + 2 * AIMG + o1) = dh23;
                        *(uint32_t*)(smem + SM_A + 3 * AIMG + o1) = dl23;
                    }
                }
        }
        __syncthreads();

        // ---- layer 2: bf16 3-term split m16n8k16 ----
        float cz1[MT][4][4], cz2[MT][4][4];
        float cd1[GRAD ? MT : 1][4][4], cd2[GRAD ? MT : 1][4][4];
        #pragma unroll
        for (int mt = 0; mt < MT; mt++)
            #pragma unroll
            for (int j = 0; j < 4; j++)
                #pragma unroll
                for (int e = 0; e < 4; e++) {
                    cz1[mt][j][e] = 0.f; cz2[mt][j][e] = 0.f;
                    if (GRAD) { cd1[mt][j][e] = 0.f; cd2[mt][j][e] = 0.f; }
                }

        #pragma unroll 1
        for (int kt = 0; kt < 8; kt++) {
            const int k0 = kt * 16;
            uint32_t bf[4][2][4];
            {
                int nr = n0 + (lane & 7) + ((lane >> 4) << 3);
                int kc = k0 + ((lane >> 3) & 1) * 8;
                #pragma unroll
                for (int img = 0; img < 4; img++)
                    #pragma unroll
                    for (int ng = 0; ng < 2; ng++)
                        LDSM4(bf[img][ng], sb + SM_W + img * 32768 + swz(nr + ng * 16, kc));
            }
            #pragma unroll
            for (int mt = 0; mt < MT; mt++) {
                int ar = m0 + mt * 16 + (lane & 7) + ((lane >> 3) & 1) * 8;
                int ac = k0 + (lane >> 4) * 8;
                uint32_t off = swz(ar, ac);
                uint32_t aYh[4], aYl[4], aDh[4], aDl[4];
                LDSM4(aYh, sb + SM_A + off);
                LDSM4(aYl, sb + SM_A + AIMG + off);
                if (GRAD) {
                    LDSM4(aDh, sb + SM_A + 2 * AIMG + off);
                    LDSM4(aDl, sb + SM_A + 3 * AIMG + off);
                }
                #pragma unroll
                for (int j = 0; j < 4; j++) {
                    const int ng = j >> 1, sub = (j & 1) * 2;
                    MMA16(cz1[mt][j], aYh, (&bf[0][ng][sub]));
                    MMA16(cz1[mt][j], aYh, (&bf[1][ng][sub]));
                    MMA16(cz1[mt][j], aYl, (&bf[0][ng][sub]));
                    MMA16(cz2[mt][j], aYh, (&bf[2][ng][sub]));
                    MMA16(cz2[mt][j], aYh, (&bf[3][ng][sub]));
                    MMA16(cz2[mt][j], aYl, (&bf[2][ng][sub]));
                    if (GRAD) {
                        MMA16(cd1[mt][j], aDh, (&bf[0][ng][sub]));
                        MMA16(cd1[mt][j], aDh, (&bf[1][ng][sub]));
                        MMA16(cd1[mt][j], aDl, (&bf[0][ng][sub]));
                        MMA16(cd2[mt][j], aDh, (&bf[2][ng][sub]));
                        MMA16(cd2[mt][j], aDh, (&bf[3][ng][sub]));
                        MMA16(cd2[mt][j], aDl, (&bf[2][ng][sub]));
                    }
                }
            }
        }

        // ---- epilogue ----
        #pragma unroll
        for (int mt = 0; mt < MT; mt++) {
            float pv0 = 0.f, pv1 = 0.f, pg0 = 0.f, pg1 = 0.f;
            #pragma unroll
            for (int j = 0; j < 4; j++) {
                float u1a = cz1[mt][j][0] + B12v[j][0];
                float u1b = cz1[mt][j][1] + B12v[j][1];
                float u1c = cz1[mt][j][2] + B12v[j][0];
                float u1d = cz1[mt][j][3] + B12v[j][1];
                float u2a = cz2[mt][j][0] + B22v[j][0];
                float u2b = cz2[mt][j][1] + B22v[j][1];
                float u2c = cz2[mt][j][2] + B22v[j][0];
                float u2d = cz2[mt][j][3] + B22v[j][1];
                pv0 = fmaf(WOv[j][0], u1a * u2a, pv0);
                pv0 = fmaf(WOv[j][1], u1b * u2b, pv0);
                pv1 = fmaf(WOv[j][0], u1c * u2c, pv1);
                pv1 = fmaf(WOv[j][1], u1d * u2d, pv1);
                if (GRAD) {
                    pg0 = fmaf(WOv[j][0], fmaf(u1a, cd2[mt][j][0], u2a * cd1[mt][j][0]), pg0);
                    pg0 = fmaf(WOv[j][1], fmaf(u1b, cd2[mt][j][1], u2b * cd1[mt][j][1]), pg0);
                    pg1 = fmaf(WOv[j][0], fmaf(u1c, cd2[mt][j][2], u2c * cd1[mt][j][2]), pg1);
                    pg1 = fmaf(WOv[j][1], fmaf(u1d, cd2[mt][j][3], u2d * cd1[mt][j][3]), pg1);
                }
            }
            pv0 += __shfl_xor_sync(0xffffffff, pv0, 1);
            pv0 += __shfl_xor_sync(0xffffffff, pv0, 2);
            pv1 += __shfl_xor_sync(0xffffffff, pv1, 1);
            pv1 += __shfl_xor_sync(0xffffffff, pv1, 2);
            if (GRAD) {
                pg0 += __shfl_xor_sync(0xffffffff, pg0, 1);
                pg0 += __shfl_xor_sync(0xffffffff, pg0, 2);
                pg1 += __shfl_xor_sync(0xffffffff, pg1, 1);
                pg1 += __shfl_xor_sync(0xffffffff, pg1, 2);
            }
            if (q4 == 0) {
                int r = m0 + mt * 16 + g4;
                sRedV[r * 4 + wn] = pv0;
                sRedV[(r + 8) * 4 + wn] = pv1;
                if (GRAD) { sRedG[r * 4 + wn] = pg0; sRedG[(r + 8) * 4 + wn] = pg1; }
            }
        }
        __syncthreads();

        if (!GRAD) {
            if (tid < 128) {
                float4 vv = *(float4*)&sRedV[tid * 4];
                float v = vv.x + vv.y + vv.z + vv.w;
                float* op = (tile < na) ? outa + (size_t)tile * 128
                                        : outb + (size_t)(tile - na) * 128;
                op[tid] = v;
            }
        } else {
            if (tid < 64) {
                float4 vv = *(float4*)&sRedV[tid * 4];
                outa[(size_t)tile * 64 + tid] = vv.x + vv.y + vv.z + vv.w;
            } else if (tid < 128) {
                int t = tid - 64;
                float4 vv = *(float4*)&sRedG[t * 4];
                out_g[(size_t)tile * 64 + t] = vv.x + vv.y + vv.z + vv.w;
            }
        }
    }
}

extern "C" void kernel_launch(void* const* d_in, const int* in_sizes, int n_in,
                              void* d_out, int out_size)
{
    const float* T      = (const float*)d_in[0];
    const float* l      = (const float*)d_in[1];
    const float* l1_dot = (const float*)d_in[2];
    const float* center = (const float*)d_in[3];
    const float* w11 = (const float*)d_in[4];
    const float* b11 = (const float*)d_in[5];
    const float* w21 = (const float*)d_in[6];
    const float* b21 = (const float*)d_in[7];
    const float* w12 = (const float*)d_in[8];
    const float* b12 = (const float*)d_in[9];
    const float* w22 = (const float*)d_in[10];
    const float* b22 = (const float*)d_in[11];
    const float* wout = (const float*)d_in[12];
    float* out = (float*)d_out;

    int nT = in_sizes[0] / 8;   // 65536
    int nL = in_sizes[1] / 8;   // 65536
    int nC = in_sizes[3] / 8;   // 512

    cudaFuncSetAttribute(net4<false>, cudaFuncAttributeMaxDynamicSharedMemorySize, SM_TOTAL);
    cudaFuncSetAttribute(net4<true>,  cudaFuncAttributeMaxDynamicSharedMemorySize, SM_TOTAL);

    float* out_vt = out;
    float* out_vy = out + nT;
    float* out_vg = out + nT + nL;
    float* out_vc = out + nT + 2 * nL;

    int naT = nT / 128;               // 512 T tiles
    int nfwd = naT + nC / 128;        // + 4 center tiles
    int ngrad = nL / 64;              // 1024 grad tiles

    prep_kernel<<<5, 256>>>(w12, w22, w11, w21);
    net4<false><<<148, TPB, SM_TOTAL>>>(T, center, nullptr,
                                        b11, b21, b12, b22, wout,
                                        out_vt, out_vc, nullptr, nfwd, naT);
    net4<true><<<148, TPB, SM_TOTAL>>>(l, nullptr, l1_dot,
                                       b11, b21, b12, b22, wout,
                                       out_vy, nullptr, out_vg, ngrad, ngrad);
}

// round 11
// speedup vs baseline: 2.9574x; 1.0372x over previous
#include <cuda_runtime.h>
#include <cuda_bf16.h>
#include <cstdint>

#define TPB 256

__device__ __forceinline__ uint32_t smem_u32(const void* p) {
    uint32_t a;
    asm("{ .reg .u64 t; cvta.to.shared.u64 t, %1; cvt.u32.u64 %0, t; }" : "=r"(a) : "l"(p));
    return a;
}

#define LDSM4(r, addr) \
    asm volatile("ldmatrix.sync.aligned.m8n8.x4.shared.b16 {%0,%1,%2,%3}, [%4];" \
        : "=r"((r)[0]), "=r"((r)[1]), "=r"((r)[2]), "=r"((r)[3]) : "r"(addr))
#define LDSM2(r, addr) \
    asm volatile("ldmatrix.sync.aligned.m8n8.x2.shared.b16 {%0,%1}, [%2];" \
        : "=r"((r)[0]), "=r"((r)[1]) : "r"(addr))

#define MMA16(c, a, b) \
    asm volatile("mma.sync.aligned.m16n8k16.row.col.f32.bf16.bf16.f32 " \
        "{%0,%1,%2,%3}, {%4,%5,%6,%7}, {%8,%9}, {%0,%1,%2,%3};" \
        : "+f"((c)[0]), "+f"((c)[1]), "+f"((c)[2]), "+f"((c)[3]) \
        : "r"((a)[0]), "r"((a)[1]), "r"((a)[2]), "r"((a)[3]), "r"((b)[0]), "r"((b)[1]))
#define MMA8(c, a, b) \
    asm volatile("mma.sync.aligned.m16n8k8.row.col.f32.bf16.bf16.f32 " \
        "{%0,%1,%2,%3}, {%4,%5}, {%6}, {%0,%1,%2,%3};" \
        : "+f"((c)[0]), "+f"((c)[1]), "+f"((c)[2]), "+f"((c)[3]) \
        : "r"((a)[0]), "r"((a)[1]), "r"(b))

// swizzled byte offset in a [rows x 128] bf16 tile, 256B rows, 16B-chunk XOR swizzle
__device__ __forceinline__ uint32_t swz(int row, int col) {
    return (uint32_t)(row * 256 + ((((col >> 3) ^ (row & 7)) & 15) << 4) + (col & 7) * 2);
}

// split a,b into bf16 hi-pair (return) and lo-pair (out param)
__device__ __forceinline__ uint32_t packsplit(float a, float b, uint32_t& lo) {
    __nv_bfloat16 ah = __float2bfloat16_rn(a), bh = __float2bfloat16_rn(b);
    __nv_bfloat16 al = __float2bfloat16_rn(a - __bfloat162float(ah));
    __nv_bfloat16 bl = __float2bfloat16_rn(b - __bfloat162float(bh));
    lo = (uint32_t)__bfloat16_as_ushort(al) | ((uint32_t)__bfloat16_as_ushort(bl) << 16);
    return (uint32_t)__bfloat16_as_ushort(ah) | ((uint32_t)__bfloat16_as_ushort(bh) << 16);
}

// ---------------- smem layout (bytes) ----------------
#define SM_W     0          // layer-2 W images: 4 x 32768 [W1h, W1l, W2h, W2l]
#define SM_A     131072     // A images: 64KB (fwd 2x32KB, grad 4x16KB)
#define SM_X     196608     // X images: 4 x 2048
#define SM_W1    204800     // layer-1 W images: 4 x 2048 [W11h, W11l, W21h, W21l]
#define SM_CONST 212992     // b11,b21,b12,b22,wout: 5 x 512
#define SM_RED   215552     // 2048
#define SM_TOTAL 217600

template <bool GRAD>
__device__ __forceinline__ void do_tile(
    char* smem, uint32_t sb, int tile,
    const float* __restrict__ xa, const float* __restrict__ xb,
    const float* __restrict__ xdot,
    float* __restrict__ outa, float* __restrict__ outb,
    float* __restrict__ out_g, int na,
    const float (&B11c)[4][2], const float (&B21c)[4][2],
    const float (&B12v)[4][2], const float (&B22v)[4][2],
    const float (&WOv)[4][2], const uint32_t (&w1f)[4][4])
{
    const int tid = threadIdx.x;
    const int wid = tid >> 5, lane = tid & 31;
    const int g4 = lane >> 2, q4 = lane & 3;

    constexpr int SPT  = GRAD ? 64 : 128;   // samples per tile
    constexpr int MT   = GRAD ? 2 : 4;      // 16-row m-tiles per warp
    constexpr int AIMG = GRAD ? 16384 : 32768;

    const int wm = wid & 1, wn = wid >> 1;
    const int m0 = wm * (SPT / 2);
    const int n0 = wn * 32;

    float* sRedV = (float*)(smem + SM_RED);
    float* sRedG = sRedV + 256;

    // ---- stage X images (bf16 hi/lo split) ----
    if (tid < 128) {
        const float* xp;
        uint32_t xoff;
        int t;
        if (!GRAD) {
            t = tid;
            xp = (tile < na) ? xa + (size_t)tile * (128 * 8)
                             : xb + (size_t)(tile - na) * (128 * 8);
            xoff = 0;
        } else {
            t = tid & 63;
            xp = (tid < 64) ? xa + (size_t)tile * (64 * 8)
                            : xdot + (size_t)tile * (64 * 8);
            xoff = (tid < 64) ? 0 : 4096;
        }
        const float4* g = (const float4*)(xp + (size_t)t * 8);
        float4 v0 = g[0], v1 = g[1];
        float v[8] = {v0.x, v0.y, v0.z, v0.w, v1.x, v1.y, v1.z, v1.w};
        uint32_t hi[4], lo[4];
        #pragma unroll
        for (int i = 0; i < 4; i++) hi[i] = packsplit(v[2 * i], v[2 * i + 1], lo[i]);
        *(uint4*)(smem + SM_X + xoff + t * 16) = make_uint4(hi[0], hi[1], hi[2], hi[3]);
        *(uint4*)(smem + SM_X + xoff + 2048 + t * 16) = make_uint4(lo[0], lo[1], lo[2], lo[3]);
    }
    __syncthreads();

    // ---- layer 1 via m16n8k8 MMA ----
    {
        float z1[MT][4][4], z2[MT][4][4];
        float d1[GRAD ? MT : 1][4][4], d2[GRAD ? MT : 1][4][4];
        #pragma unroll
        for (int mt = 0; mt < MT; mt++)
            #pragma unroll
            for (int j = 0; j < 4; j++)
                #pragma unroll
                for (int e = 0; e < 4; e++) {
                    z1[mt][j][e] = 0.f; z2[mt][j][e] = 0.f;
                    if (GRAD) { d1[mt][j][e] = 0.f; d2[mt][j][e] = 0.f; }
                }
        #pragma unroll
        for (int mt = 0; mt < MT; mt++) {
            uint32_t xh[2], xl[2], xdh[2], xdl[2];
            uint32_t xr = (uint32_t)(m0 + mt * 16 + (lane & 15)) * 16;
            LDSM2(xh, sb + SM_X + xr);
            LDSM2(xl, sb + SM_X + 2048 + xr);
            if (GRAD) {
                LDSM2(xdh, sb + SM_X + 4096 + xr);
                LDSM2(xdl, sb + SM_X + 6144 + xr);
            }
            #pragma unroll
            for (int j = 0; j < 4; j++) {
                MMA8(z1[mt][j], xh, w1f[0][j]);
                MMA8(z1[mt][j], xh, w1f[1][j]);
                MMA8(z1[mt][j], xl, w1f[0][j]);
                MMA8(z2[mt][j], xh, w1f[2][j]);
                MMA8(z2[mt][j], xh, w1f[3][j]);
                MMA8(z2[mt][j], xl, w1f[2][j]);
                if (GRAD) {
                    MMA8(d1[mt][j], xdh, w1f[0][j]);
                    MMA8(d1[mt][j], xdh, w1f[1][j]);
                    MMA8(d1[mt][j], xdl, w1f[0][j]);
                    MMA8(d2[mt][j], xdh, w1f[2][j]);
                    MMA8(d2[mt][j], xdh, w1f[3][j]);
                    MMA8(d2[mt][j], xdl, w1f[2][j]);
                }
            }
        }
        // gate + split + store A images
        #pragma unroll
        for (int mt = 0; mt < MT; mt++)
            #pragma unroll
            for (int j = 0; j < 4; j++) {
                float u1[4], u2[4], y[4];
                #pragma unroll
                for (int e = 0; e < 4; e++) {
                    u1[e] = z1[mt][j][e] + B11c[j][e & 1];
                    u2[e] = z2[mt][j][e] + B21c[j][e & 1];
                    y[e] = u1[e] * u2[e];
                }
                int row = m0 + mt * 16 + g4;
                int col = n0 + j * 8 + q4 * 2;
                uint32_t o0 = swz(row, col), o1 = swz(row + 8, col);
                uint32_t l01, h01 = packsplit(y[0], y[1], l01);
                uint32_t l23, h23 = packsplit(y[2], y[3], l23);
                *(uint32_t*)(smem + SM_A + o0) = h01;
                *(uint32_t*)(smem + SM_A + AIMG + o0) = l01;
                *(uint32_t*)(smem + SM_A + o1) = h23;
                *(uint32_t*)(smem + SM_A + AIMG + o1) = l23;
                if (GRAD) {
                    float dy[4];
                    #pragma unroll
                    for (int e = 0; e < 4; e++)
                        dy[e] = fmaf(u1[e], d2[mt][j][e], u2[e] * d1[mt][j][e]);
                    uint32_t dl01, dh01 = packsplit(dy[0], dy[1], dl01);
                    uint32_t dl23, dh23 = packsplit(dy[2], dy[3], dl23);
                    *(uint32_t*)(smem + SM_A + 2 * AIMG + o0) = dh01;
                    *(uint32_t*)(smem + SM_A + 3 * AIMG + o0) = dl01;
                    *(uint32_t*)(smem + SM_A + 2 * AIMG + o1) = dh23;
                    *(uint32_t*)(smem + SM_A + 3 * AIMG + o1) = dl23;
                }
            }
    }
    __syncthreads();

    // ---- layer 2: bf16 3-term split m16n8k16 ----
    float cz1[MT][4][4], cz2[MT][4][4];
    float cd1[GRAD ? MT : 1][4][4], cd2[GRAD ? MT : 1][4][4];
    #pragma unroll
    for (int mt = 0; mt < MT; mt++)
        #pragma unroll
        for (int j = 0; j < 4; j++)
            #pragma unroll
            for (int e = 0; e < 4; e++) {
                cz1[mt][j][e] = 0.f; cz2[mt][j][e] = 0.f;
                if (GRAD) { cd1[mt][j][e] = 0.f; cd2[mt][j][e] = 0.f; }
            }

    #pragma unroll 1
    for (int kt = 0; kt < 8; kt++) {
        const int k0 = kt * 16;
        uint32_t bf[4][2][4];
        {
            int nr = n0 + (lane & 7) + ((lane >> 4) << 3);
            int kc = k0 + ((lane >> 3) & 1) * 8;
            #pragma unroll
            for (int img = 0; img < 4; img++)
                #pragma unroll
                for (int ng = 0; ng < 2; ng++)
                    LDSM4(bf[img][ng], sb + SM_W + img * 32768 + swz(nr + ng * 16, kc));
        }
        #pragma unroll
        for (int mt = 0; mt < MT; mt++) {
            int ar = m0 + mt * 16 + (lane & 7) + ((lane >> 3) & 1) * 8;
            int ac = k0 + (lane >> 4) * 8;
            uint32_t off = swz(ar, ac);
            uint32_t aYh[4], aYl[4], aDh[4], aDl[4];
            LDSM4(aYh, sb + SM_A + off);
            LDSM4(aYl, sb + SM_A + AIMG + off);
            if (GRAD) {
                LDSM4(aDh, sb + SM_A + 2 * AIMG + off);
                LDSM4(aDl, sb + SM_A + 3 * AIMG + off);
            }
            #pragma unroll
            for (int j = 0; j < 4; j++) {
                const int ng = j >> 1, sub = (j & 1) * 2;
                MMA16(cz1[mt][j], aYh, (&bf[0][ng][sub]));
                MMA16(cz1[mt][j], aYh, (&bf[1][ng][sub]));
                MMA16(cz1[mt][j], aYl, (&bf[0][ng][sub]));
                MMA16(cz2[mt][j], aYh, (&bf[2][ng][sub]));
                MMA16(cz2[mt][j], aYh, (&bf[3][ng][sub]));
                MMA16(cz2[mt][j], aYl, (&bf[2][ng][sub]));
                if (GRAD) {
                    MMA16(cd1[mt][j], aDh, (&bf[0][ng][sub]));
                    MMA16(cd1[mt][j], aDh, (&bf[1][ng][sub]));
                    MMA16(cd1[mt][j], aDl, (&bf[0][ng][sub]));
                    MMA16(cd2[mt][j], aDh, (&bf[2][ng][sub]));
                    MMA16(cd2[mt][j], aDh, (&bf[3][ng][sub]));
                    MMA16(cd2[mt][j], aDl, (&bf[2][ng][sub]));
                }
            }
        }
    }

    // ---- epilogue ----
    #pragma unroll
    for (int mt = 0; mt < MT; mt++) {
        float pv0 = 0.f, pv1 = 0.f, pg0 = 0.f, pg1 = 0.f;
        #pragma unroll
        for (int j = 0; j < 4; j++) {
            float u1a = cz1[mt][j][0] + B12v[j][0];
            float u1b = cz1[mt][j][1] + B12v[j][1];
            float u1c = cz1[mt][j][2] + B12v[j][0];
            float u1d = cz1[mt][j][3] + B12v[j][1];
            float u2a = cz2[mt][j][0] + B22v[j][0];
            float u2b = cz2[mt][j][1] + B22v[j][1];
            float u2c = cz2[mt][j][2] + B22v[j][0];
            float u2d = cz2[mt][j][3] + B22v[j][1];
            pv0 = fmaf(WOv[j][0], u1a * u2a, pv0);
            pv0 = fmaf(WOv[j][1], u1b * u2b, pv0);
            pv1 = fmaf(WOv[j][0], u1c * u2c, pv1);
            pv1 = fmaf(WOv[j][1], u1d * u2d, pv1);
            if (GRAD) {
                pg0 = fmaf(WOv[j][0], fmaf(u1a, cd2[mt][j][0], u2a * cd1[mt][j][0]), pg0);
                pg0 = fmaf(WOv[j][1], fmaf(u1b, cd2[mt][j][1], u2b * cd1[mt][j][1]), pg0);
                pg1 = fmaf(WOv[j][0], fmaf(u1c, cd2[mt][j][2], u2c * cd1[mt][j][2]), pg1);
                pg1 = fmaf(WOv[j][1], fmaf(u1d, cd2[mt][j][3], u2d * cd1[mt][j][3]), pg1);
            }
        }
        pv0 += __shfl_xor_sync(0xffffffff, pv0, 1);
        pv0 += __shfl_xor_sync(0xffffffff, pv0, 2);
        pv1 += __shfl_xor_sync(0xffffffff, pv1, 1);
        pv1 += __shfl_xor_sync(0xffffffff, pv1, 2);
        if (GRAD) {
            pg0 += __shfl_xor_sync(0xffffffff, pg0, 1);
            pg0 += __shfl_xor_sync(0xffffffff, pg0, 2);
            pg1 += __shfl_xor_sync(0xffffffff, pg1, 1);
            pg1 += __shfl_xor_sync(0xffffffff, pg1, 2);
        }
        if (q4 == 0) {
            int r = m0 + mt * 16 + g4;
            sRedV[r * 4 + wn] = pv0;
            sRedV[(r + 8) * 4 + wn] = pv1;
            if (GRAD) { sRedG[r * 4 + wn] = pg0; sRedG[(r + 8) * 4 + wn] = pg1; }
        }
    }
    __syncthreads();

    if (!GRAD) {
        if (tid < 128) {
            float4 vv = *(float4*)&sRedV[tid * 4];
            float v = vv.x + vv.y + vv.z + vv.w;
            float* op = (tile < na) ? outa + (size_t)tile * 128
                                    : outb + (size_t)(tile - na) * 128;
            op[tid] = v;
        }
    } else {
        if (tid < 64) {
            float4 vv = *(float4*)&sRedV[tid * 4];
            outa[(size_t)tile * 64 + tid] = vv.x + vv.y + vv.z + vv.w;
        } else if (tid < 128) {
            int t = tid - 64;
            float4 vv = *(float4*)&sRedG[t * 4];
            out_g[(size_t)tile * 64 + t] = vv.x + vv.y + vv.z + vv.w;
        }
    }
}

__global__ __launch_bounds__(TPB, 1)
void netall(const float* __restrict__ T, const float* __restrict__ l,
            const float* __restrict__ l1_dot, const float* __restrict__ center,
            const float* __restrict__ w11, const float* __restrict__ b11,
            const float* __restrict__ w21, const float* __restrict__ b21,
            const float* __restrict__ w12, const float* __restrict__ b12,
            const float* __restrict__ w22, const float* __restrict__ b22,
            const float* __restrict__ wout,
            float* __restrict__ out_vt, float* __restrict__ out_vy,
            float* __restrict__ out_vg, float* __restrict__ out_vc,
            int naT, int nfwd, int ntot)
{
    extern __shared__ char smem[];
    const uint32_t sb = smem_u32(smem);
    const int tid = threadIdx.x;
    const int wid = tid >> 5, lane = tid & 31;
    const int q4 = lane & 3;
    const int wn = wid >> 1;
    const int n0 = wn * 32;

    float* sC = (float*)(smem + SM_CONST);

    // ---- build weight images in smem from global fp32 weights ----
    for (int idx = tid; idx < 8192; idx += TPB) {
        int o = idx >> 6, c = (idx & 63) * 2;
        uint32_t so = swz(o, c);
        {
            float a = w12[o * 128 + c], b = w12[o * 128 + c + 1];
            uint32_t pl, ph = packsplit(a, b, pl);
            *(uint32_t*)(smem + SM_W + so) = ph;
            *(uint32_t*)(smem + SM_W + 32768 + so) = pl;
        }
        {
            float a = w22[o * 128 + c], b = w22[o * 128 + c + 1];
            uint32_t pl, ph = packsplit(a, b, pl);
            *(uint32_t*)(smem + SM_W + 65536 + so) = ph;
            *(uint32_t*)(smem + SM_W + 98304 + so) = pl;
        }
    }
    for (int idx = tid; idx < 512; idx += TPB) {
        int r = idx >> 2, cp = idx & 3;
        {
            float a = w11[r * 8 + cp * 2], b = w11[r * 8 + cp * 2 + 1];
            uint32_t pl, ph = packsplit(a, b, pl);
            ((uint32_t*)(smem + SM_W1))[r * 4 + cp] = ph;
            ((uint32_t*)(smem + SM_W1 + 2048))[r * 4 + cp] = pl;
        }
        {
            float a = w21[r * 8 + cp * 2], b = w21[r * 8 + cp * 2 + 1];
            uint32_t pl, ph = packsplit(a, b, pl);
            ((uint32_t*)(smem + SM_W1 + 4096))[r * 4 + cp] = ph;
            ((uint32_t*)(smem + SM_W1 + 6144))[r * 4 + cp] = pl;
        }
    }
    if (tid < 128) {
        sC[tid] = b11[tid]; sC[128 + tid] = b21[tid];
        sC[256 + tid] = b12[tid]; sC[384 + tid] = b22[tid];
        sC[512 + tid] = wout[tid];
    }
    __syncthreads();

    // hoisted per-thread column constants
    float B11c[4][2], B21c[4][2], B12v[4][2], B22v[4][2], WOv[4][2];
    #pragma unroll
    for (int j = 0; j < 4; j++)
        #pragma unroll
        for (int e = 0; e < 2; e++) {
            int c = n0 + j * 8 + q4 * 2 + e;
            B11c[j][e] = sC[c]; B21c[j][e] = sC[128 + c];
            B12v[j][e] = sC[256 + c]; B22v[j][e] = sC[384 + c];
            WOv[j][e] = sC[512 + c];
        }
    // hoisted layer-1 weight b-frags
    uint32_t w1f[4][4];
    #pragma unroll
    for (int img = 0; img < 4; img++)
        #pragma unroll
        for (int ng = 0; ng < 2; ng++)
            LDSM2(&w1f[img][ng * 2],
                  sb + SM_W1 + img * 2048 + (uint32_t)(n0 + ng * 16 + (lane & 15)) * 16);

    for (int t = blockIdx.x; t < ntot; t += gridDim.x) {
        __syncthreads();
        if (t < nfwd) {
            do_tile<false>(smem, sb, t, T, center, nullptr,
                           out_vt, out_vc, nullptr, naT,
                           B11c, B21c, B12v, B22v, WOv, w1f);
        } else {
            do_tile<true>(smem, sb, t - nfwd, l, nullptr, l1_dot,
                          out_vy, nullptr, out_vg, 0,
                          B11c, B21c, B12v, B22v, WOv, w1f);
        }
    }
}

extern "C" void kernel_launch(void* const* d_in, const int* in_sizes, int n_in,
                              void* d_out, int out_size)
{
    const float* T      = (const float*)d_in[0];
    const float* l      = (const float*)d_in[1];
    const float* l1_dot = (const float*)d_in[2];
    const float* center = (const float*)d_in[3];
    const float* w11 = (const float*)d_in[4];
    const float* b11 = (const float*)d_in[5];
    const float* w21 = (const float*)d_in[6];
    const float* b21 = (const float*)d_in[7];
    const float* w12 = (const float*)d_in[8];
    const float* b12 = (const float*)d_in[9];
    const float* w22 = (const float*)d_in[10];
    const float* b22 = (const float*)d_in[11];
    const float* wout = (const float*)d_in[12];
    float* out = (float*)d_out;

    int nT = in_sizes[0] / 8;   // 65536
    int nL = in_sizes[1] / 8;   // 65536
    int nC = in_sizes[3] / 8;   // 512

    cudaFuncSetAttribute(netall, cudaFuncAttributeMaxDynamicSharedMemorySize, SM_TOTAL);

    float* out_vt = out;
    float* out_vy = out + nT;
    float* out_vg = out + nT + nL;
    float* out_vc = out + nT + 2 * nL;

    int naT = nT / 128;               // 512 T tiles
    int nfwd = naT + nC / 128;        // + 4 center tiles = 516
    int ngrad = nL / 64;              // 1024 grad tiles
    int ntot = nfwd + ngrad;          // 1540

    netall<<<148, TPB, SM_TOTAL>>>(T, l, l1_dot, center,
                                   w11, b11, w21, b21, w12, b12, w22, b22, wout,
                                   out_vt, out_vy, out_vg, out_vc,
                                   naT, nfwd, ntot);
}

// round 16
// speedup vs baseline: 3.7864x; 1.2803x over previous
#include <cuda_runtime.h>
#include <cuda_bf16.h>
#include <cstdint>

#define TPB 256

__device__ __forceinline__ uint32_t smem_u32(const void* p) {
    uint32_t a;
    asm("{ .reg .u64 t; cvta.to.shared.u64 t, %1; cvt.u32.u64 %0, t; }" : "=r"(a) : "l"(p));
    return a;
}

#define LDSM4(r, addr) \
    asm volatile("ldmatrix.sync.aligned.m8n8.x4.shared.b16 {%0,%1,%2,%3}, [%4];" \
        : "=r"((r)[0]), "=r"((r)[1]), "=r"((r)[2]), "=r"((r)[3]) : "r"(addr))
#define LDSM2(r, addr) \
    asm volatile("ldmatrix.sync.aligned.m8n8.x2.shared.b16 {%0,%1}, [%2];" \
        : "=r"((r)[0]), "=r"((r)[1]) : "r"(addr))

#define MMA16(c, a, b) \
    asm volatile("mma.sync.aligned.m16n8k16.row.col.f32.bf16.bf16.f32 " \
        "{%0,%1,%2,%3}, {%4,%5,%6,%7}, {%8,%9}, {%0,%1,%2,%3};" \
        : "+f"((c)[0]), "+f"((c)[1]), "+f"((c)[2]), "+f"((c)[3]) \
        : "r"((a)[0]), "r"((a)[1]), "r"((a)[2]), "r"((a)[3]), "r"((b)[0]), "r"((b)[1]))
#define MMA8(c, a, b) \
    asm volatile("mma.sync.aligned.m16n8k8.row.col.f32.bf16.bf16.f32 " \
        "{%0,%1,%2,%3}, {%4,%5}, {%6}, {%0,%1,%2,%3};" \
        : "+f"((c)[0]), "+f"((c)[1]), "+f"((c)[2]), "+f"((c)[3]) \
        : "r"((a)[0]), "r"((a)[1]), "r"(b))

// swizzled byte offset in a [rows x 128] bf16 tile, 256B rows, 16B-chunk XOR swizzle
__device__ __forceinline__ uint32_t swz(int row, int col) {
    return (uint32_t)(row * 256 + ((((col >> 3) ^ (row & 7)) & 15) << 4) + (col & 7) * 2);
}

// split a,b into bf16 hi-pair (return) and lo-pair (out param)
__device__ __forceinline__ uint32_t packsplit(float a, float b, uint32_t& lo) {
    __nv_bfloat16 ah = __float2bfloat16_rn(a), bh = __float2bfloat16_rn(b);
    __nv_bfloat16 al = __float2bfloat16_rn(a - __bfloat162float(ah));
    __nv_bfloat16 bl = __float2bfloat16_rn(b - __bfloat162float(bh));
    lo = (uint32_t)__bfloat16_as_ushort(al) | ((uint32_t)__bfloat16_as_ushort(bl) << 16);
    return (uint32_t)__bfloat16_as_ushort(ah) | ((uint32_t)__bfloat16_as_ushort(bh) << 16);
}

// reconstruct fp32 pair from hi/lo bf16 pairs
__device__ __forceinline__ float2 bfpair(uint32_t h, uint32_t l) {
    float2 r;
    r.x = __bfloat162float(__ushort_as_bfloat16((unsigned short)(h & 0xFFFF))) +
          __bfloat162float(__ushort_as_bfloat16((unsigned short)(l & 0xFFFF)));
    r.y = __bfloat162float(__ushort_as_bfloat16((unsigned short)(h >> 16))) +
          __bfloat162float(__ushort_as_bfloat16((unsigned short)(l >> 16)));
    return r;
}

// ---------------- device scratch ----------------
__device__ uint32_t gMimg[2][8192];  // M = W1^T diag(wo) W2: [Mh, Ml] 128x128 bf16 swizzled
__device__ float gCvec[129];         // c[128], c0

__global__ void prep_kernel(const float* __restrict__ w12, const float* __restrict__ w22,
                            const float* __restrict__ b12, const float* __restrict__ b22,
                            const float* __restrict__ wout) {
    __shared__ float sWJ[128];
    int j = blockIdx.x, t = threadIdx.x;
    if (j < 128) {
        // image row j holds M[:, j] along k=i:  B[n=j][k=i] = M_ij
        sWJ[t] = wout[t] * w22[t * 128 + j];
        __syncthreads();
        if (t < 64) {
            int i0 = t * 2;
            float m0 = 0.f, m1 = 0.f;
            for (int o = 0; o < 128; o++) {
                float wj = sWJ[o];
                m0 = fmaf(w12[o * 128 + i0], wj, m0);
                m1 = fmaf(w12[o * 128 + i0 + 1], wj, m1);
            }
            uint32_t pl, ph = packsplit(m0, m1, pl);
            gMimg[0][swz(j, i0) >> 2] = ph;
            gMimg[1][swz(j, i0) >> 2] = pl;
        }
    } else {
        float acc = 0.f;
        for (int o = 0; o < 128; o++)
            acc = fmaf(wout[o],
                       fmaf(w12[o * 128 + t], b22[o], w22[o * 128 + t] * b12[o]), acc);
        gCvec[t] = acc;
        if (t == 0) {
            float cc = 0.f;
            for (int o = 0; o < 128; o++) cc = fmaf(wout[o] * b12[o], b22[o], cc);
            gCvec[128] = cc;
        }
    }
}

// ---------------- smem layout (bytes) ----------------
#define SM_W     0          // M images: Mh, Ml (2 x 32768)
#define SM_A     65536      // A images: 64KB (fwd 2x32KB; grad 4x16KB)
#define SM_X     131072     // X images: 4 x 2048
#define SM_W1    139264     // layer-1 W images: 4 x 2048
#define SM_CONST 147456     // b11(512), b21(512), c(512), c0(+pad 512)
#define SM_RED   149504     // sRedV 1024, sRedG 1024
#define SM_YC    151552     // sYC 1024, sDC 1024
#define SM_TOTAL 153600

template <bool GRAD>
__device__ __forceinline__ void do_tile(
    char* smem, uint32_t sb, int tile,
    const float* __restrict__ xa, const float* __restrict__ xb,
    const float* __restrict__ xdot,
    float* __restrict__ outa, float* __restrict__ outb,
    float* __restrict__ out_g, int na,
    const float (&B11c)[4][2], const float (&B21c)[4][2],
    const float (&Cc)[4][2], float c0, const uint32_t (&w1f)[4][4])
{
    const int tid = threadIdx.x;
    const int wid = tid >> 5, lane = tid & 31;
    const int g4 = lane >> 2, q4 = lane & 3;

    constexpr int SPT  = GRAD ? 64 : 128;
    constexpr int MT   = GRAD ? 2 : 4;
    constexpr int AIMG = GRAD ? 16384 : 32768;

    const int wm = wid & 1, wn = wid >> 1;
    const int m0 = wm * (SPT / 2);
    const int n0 = wn * 32;

    float* sRedV = (float*)(smem + SM_RED);
    float* sRedG = sRedV + 256;
    float* sYC   = (float*)(smem + SM_YC);   // [SPT][4] wn-partials of y.c
    float* sDC   = sYC + 256;                // [64][4]  wn-partials of d.c (grad)

    // ---- stage X images (bf16 hi/lo split) ----
    if (tid < 128) {
        const float* xp;
        uint32_t xoff;
        int t;
        if (!GRAD) {
            t = tid;
            xp = (tile < na) ? xa + (size_t)tile * (128 * 8)
                             : xb + (size_t)(tile - na) * (128 * 8);
            xoff = 0;
        } else {
            t = tid & 63;
            xp = (tid < 64) ? xa + (size_t)tile * (64 * 8)
                            : xdot + (size_t)tile * (64 * 8);
            xoff = (tid < 64) ? 0 : 4096;
        }
        const float4* g = (const float4*)(xp + (size_t)t * 8);
        float4 v0 = g[0], v1 = g[1];
        float v[8] = {v0.x, v0.y, v0.z, v0.w, v1.x, v1.y, v1.z, v1.w};
        uint32_t hi[4], lo[4];
        #pragma unroll
        for (int i = 0; i < 4; i++) hi[i] = packsplit(v[2 * i], v[2 * i + 1], lo[i]);
        *(uint4*)(smem + SM_X + xoff + t * 16) = make_uint4(hi[0], hi[1], hi[2], hi[3]);
        *(uint4*)(smem + SM_X + xoff + 2048 + t * 16) = make_uint4(lo[0], lo[1], lo[2], lo[3]);
    }
    __syncthreads();

    // ---- layer 1 via m16n8k8 MMA; gate; y.c / d.c partials; store A images ----
    {
        float z1[MT][4][4], z2[MT][4][4];
        float d1[GRAD ? MT : 1][4][4], d2[GRAD ? MT : 1][4][4];
        #pragma unroll
        for (int mt = 0; mt < MT; mt++)
            #pragma unroll
            for (int j = 0; j < 4; j++)
                #pragma unroll
                for (int e = 0; e < 4; e++) {
                    z1[mt][j][e] = 0.f; z2[mt][j][e] = 0.f;
                    if (GRAD) { d1[mt][j][e] = 0.f; d2[mt][j][e] = 0.f; }
                }
        #pragma unroll
        for (int mt = 0; mt < MT; mt++) {
            uint32_t xh[2], xl[2], xdh[2], xdl[2];
            uint32_t xr = (uint32_t)(m0 + mt * 16 + (lane & 15)) * 16;
            LDSM2(xh, sb + SM_X + xr);
            LDSM2(xl, sb + SM_X + 2048 + xr);
            if (GRAD) {
                LDSM2(xdh, sb + SM_X + 4096 + xr);
                LDSM2(xdl, sb + SM_X + 6144 + xr);
            }
            #pragma unroll
            for (int j = 0; j < 4; j++) {
                MMA8(z1[mt][j], xh, w1f[0][j]);
                MMA8(z1[mt][j], xh, w1f[1][j]);
                MMA8(z1[mt][j], xl, w1f[0][j]);
                MMA8(z2[mt][j], xh, w1f[2][j]);
                MMA8(z2[mt][j], xh, w1f[3][j]);
                MMA8(z2[mt][j], xl, w1f[2][j]);
                if (GRAD) {
                    MMA8(d1[mt][j], xdh, w1f[0][j]);
                    MMA8(d1[mt][j], xdh, w1f[1][j]);
                    MMA8(d1[mt][j], xdl, w1f[0][j]);
                    MMA8(d2[mt][j], xdh, w1f[2][j]);
                    MMA8(d2[mt][j], xdh, w1f[3][j]);
                    MMA8(d2[mt][j], xdl, w1f[2][j]);
                }
            }
        }
        #pragma unroll
        for (int mt = 0; mt < MT; mt++) {
            float yc0 = 0.f, yc1 = 0.f, dc0 = 0.f, dc1 = 0.f;
            #pragma unroll
            for (int j = 0; j < 4; j++) {
                float u1[4], u2[4], y[4];
                #pragma unroll
                for (int e = 0; e < 4; e++) {
                    u1[e] = z1[mt][j][e] + B11c[j][e & 1];
                    u2[e] = z2[mt][j][e] + B21c[j][e & 1];
                    y[e] = u1[e] * u2[e];
                }
                yc0 = fmaf(y[0], Cc[j][0], fmaf(y[1], Cc[j][1], yc0));
                yc1 = fmaf(y[2], Cc[j][0], fmaf(y[3], Cc[j][1], yc1));
                int row = m0 + mt * 16 + g4;
                int col = n0 + j * 8 + q4 * 2;
                uint32_t o0 = swz(row, col), o1 = swz(row + 8, col);
                uint32_t l01, h01 = packsplit(y[0], y[1], l01);
                uint32_t l23, h23 = packsplit(y[2], y[3], l23);
                *(uint32_t*)(smem + SM_A + o0) = h01;
                *(uint32_t*)(smem + SM_A + AIMG + o0) = l01;
                *(uint32_t*)(smem + SM_A + o1) = h23;
                *(uint32_t*)(smem + SM_A + AIMG + o1) = l23;
                if (GRAD) {
                    float dy[4];
                    #pragma unroll
                    for (int e = 0; e < 4; e++)
                        dy[e] = fmaf(u1[e], d2[mt][j][e], u2[e] * d1[mt][j][e]);
                    dc0 = fmaf(dy[0], Cc[j][0], fmaf(dy[1], Cc[j][1], dc0));
                    dc1 = fmaf(dy[2], Cc[j][0], fmaf(dy[3], Cc[j][1], dc1));
                    uint32_t dl01, dh01 = packsplit(dy[0], dy[1], dl01);
                    uint32_t dl23, dh23 = packsplit(dy[2], dy[3], dl23);
                    *(uint32_t*)(smem + SM_A + 2 * AIMG + o0) = dh01;
                    *(uint32_t*)(smem + SM_A + 3 * AIMG + o0) = dl01;
                    *(uint32_t*)(smem + SM_A + 2 * AIMG + o1) = dh23;
                    *(uint32_t*)(smem + SM_A + 3 * AIMG + o1) = dl23;
                }
            }
            yc0 += __shfl_xor_sync(0xffffffff, yc0, 1);
            yc0 += __shfl_xor_sync(0xffffffff, yc0, 2);
            yc1 += __shfl_xor_sync(0xffffffff, yc1, 1);
            yc1 += __shfl_xor_sync(0xffffffff, yc1, 2);
            if (GRAD) {
                dc0 += __shfl_xor_sync(0xffffffff, dc0, 1);
                dc0 += __shfl_xor_sync(0xffffffff, dc0, 2);
                dc1 += __shfl_xor_sync(0xffffffff, dc1, 1);
                dc1 += __shfl_xor_sync(0xffffffff, dc1, 2);
            }
            if (q4 == 0) {
                int r = m0 + mt * 16 + g4;
                sYC[r * 4 + wn] = yc0;
                sYC[(r + 8) * 4 + wn] = yc1;
                if (GRAD) { sDC[r * 4 + wn] = dc0; sDC[(r + 8) * 4 + wn] = dc1; }
            }
        }
    }
    __syncthreads();

    // ---- layer 2: P = Y.M (and Q = D.M), bf16 3-term split ----
    float czP[MT][4][4];
    float czQ[GRAD ? MT : 1][4][4];
    #pragma unroll
    for (int mt = 0; mt < MT; mt++)
        #pragma unroll
        for (int j = 0; j < 4; j++)
            #pragma unroll
            for (int e = 0; e < 4; e++) {
                czP[mt][j][e] = 0.f;
                if (GRAD) czQ[mt][j][e] = 0.f;
            }

    #pragma unroll 1
    for (int kt = 0; kt < 8; kt++) {
        const int k0 = kt * 16;
        uint32_t bf[2][2][4];
        {
            int nr = n0 + (lane & 7) + ((lane >> 4) << 3);
            int kc = k0 + ((lane >> 3) & 1) * 8;
            #pragma unroll
            for (int img = 0; img < 2; img++)
                #pragma unroll
                for (int ng = 0; ng < 2; ng++)
                    LDSM4(bf[img][ng], sb + SM_W + img * 32768 + swz(nr + ng * 16, kc));
        }
        #pragma unroll
        for (int mt = 0; mt < MT; mt++) {
            int ar = m0 + mt * 16 + (lane & 7) + ((lane >> 3) & 1) * 8;
            int ac = k0 + (lane >> 4) * 8;
            uint32_t off = swz(ar, ac);
            uint32_t aYh[4], aYl[4], aDh[4], aDl[4];
            LDSM4(aYh, sb + SM_A + off);
            LDSM4(aYl, sb + SM_A + AIMG + off);
            if (GRAD) {
                LDSM4(aDh, sb + SM_A + 2 * AIMG + off);
                LDSM4(aDl, sb + SM_A + 3 * AIMG + off);
            }
            #pragma unroll
            for (int j = 0; j < 4; j++) {
                const int ng = j >> 1, sub = (j & 1) * 2;
                MMA16(czP[mt][j], aYh, (&bf[0][ng][sub]));
                MMA16(czP[mt][j], aYh, (&bf[1][ng][sub]));
                MMA16(czP[mt][j], aYl, (&bf[0][ng][sub]));
                if (GRAD) {
                    MMA16(czQ[mt][j], aDh, (&bf[0][ng][sub]));
                    MMA16(czQ[mt][j], aDh, (&bf[1][ng][sub]));
                    MMA16(czQ[mt][j], aDl, (&bf[0][ng][sub]));
                }
            }
        }
    }

    // ---- epilogue: v = <P,y> (+ y.c + c0); g = <Q,y> + <P,d> (+ d.c) ----
    #pragma unroll
    for (int mt = 0; mt < MT; mt++) {
        float pv0 = 0.f, pv1 = 0.f, pg0 = 0.f, pg1 = 0.f;
        int r0 = m0 + mt * 16 + g4, r1 = r0 + 8;
        #pragma unroll
        for (int j = 0; j < 4; j++) {
            int cp = n0 + j * 8 + q4 * 2;
            uint32_t s0 = swz(r0, cp), s1 = swz(r1, cp);
            float2 y0 = bfpair(*(uint32_t*)(smem + SM_A + s0),
                               *(uint32_t*)(smem + SM_A + AIMG + s0));
            float2 y1 = bfpair(*(uint32_t*)(smem + SM_A + s1),
                               *(uint32_t*)(smem + SM_A + AIMG + s1));
            pv0 = fmaf(czP[mt][j][0], y0.x, fmaf(czP[mt][j][1], y0.y, pv0));
            pv1 = fmaf(czP[mt][j][2], y1.x, fmaf(czP[mt][j][3], y1.y, pv1));
            if (GRAD) {
                float2 dd0 = bfpair(*(uint32_t*)(smem + SM_A + 2 * AIMG + s0),
                                    *(uint32_t*)(smem + SM_A + 3 * AIMG + s0));
                float2 dd1 = bfpair(*(uint32_t*)(smem + SM_A + 2 * AIMG + s1),
                                    *(uint32_t*)(smem + SM_A + 3 * AIMG + s1));
                pg0 = fmaf(czQ[mt][j][0], y0.x, fmaf(czQ[mt][j][1], y0.y, pg0));
                pg0 = fmaf(czP[mt][j][0], dd0.x, fmaf(czP[mt][j][1], dd0.y, pg0));
                pg1 = fmaf(czQ[mt][j][2], y1.x, fmaf(czQ[mt][j][3], y1.y, pg1));
                pg1 = fmaf(czP[mt][j][2], dd1.x, fmaf(czP[mt][j][3], dd1.y, pg1));
            }
        }
        pv0 += __shfl_xor_sync(0xffffffff, pv0, 1);
        pv0 += __shfl_xor_sync(0xffffffff, pv0, 2);
        pv1 += __shfl_xor_sync(0xffffffff, pv1, 1);
        pv1 += __shfl_xor_sync(0xffffffff, pv1, 2);
        if (GRAD) {
            pg0 += __shfl_xor_sync(0xffffffff, pg0, 1);
            pg0 += __shfl_xor_sync(0xffffffff, pg0, 2);
            pg1 += __shfl_xor_sync(0xffffffff, pg1, 1);
            pg1 += __shfl_xor_sync(0xffffffff, pg1, 2);
        }
        if (q4 == 0) {
            sRedV[r0 * 4 + wn] = pv0;
            sRedV[r1 * 4 + wn] = pv1;
            if (GRAD) { sRedG[r0 * 4 + wn] = pg0; sRedG[r1 * 4 + wn] = pg1; }
        }
    }
    __syncthreads();

    if (!GRAD) {
        if (tid < 128) {
            float4 vv = *(float4*)&sRedV[tid * 4];
            float4 yy = *(float4*)&sYC[tid * 4];
            float v = vv.x + vv.y + vv.z + vv.w + yy.x + yy.y + yy.z + yy.w + c0;
            float* op = (tile < na) ? outa + (size_t)tile * 128
                                    : outb + (size_t)(tile - na) * 128;
            op[tid] = v;
        }
    } else {
        if (tid < 64) {
            float4 vv = *(float4*)&sRedV[tid * 4];
            float4 yy = *(float4*)&sYC[tid * 4];
            outa[(size_t)tile * 64 + tid] =
                vv.x + vv.y + vv.z + vv.w + yy.x + yy.y + yy.z + yy.w + c0;
        } else if (tid < 128) {
            int t = tid - 64;
            float4 gg = *(float4*)&sRedG[t * 4];
            float4 dd = *(float4*)&sDC[t * 4];
            out_g[(size_t)tile * 64 + t] =
                gg.x + gg.y + gg.z + gg.w + dd.x + dd.y + dd.z + dd.w;
        }
    }
}

__global__ __launch_bounds__(TPB, 1)
void netall(const float* __restrict__ T, const float* __restrict__ l,
            const float* __restrict__ l1_dot, const float* __restrict__ center,
            const float* __restrict__ w11, const float* __restrict__ b11,
            const float* __restrict__ w21, const float* __restrict__ b21,
            float* __restrict__ out_vt, float* __restrict__ out_vy,
            float* __restrict__ out_vg, float* __restrict__ out_vc,
            int naT, int nfwd, int ntot)
{
    extern __shared__ char smem[];
    const uint32_t sb = smem_u32(smem);
    const int tid = threadIdx.x;
    const int wid = tid >> 5, lane = tid & 31;
    const int q4 = lane & 3;
    const int wn = wid >> 1;
    const int n0 = wn * 32;

    float* sC = (float*)(smem + SM_CONST);

    // ---- build resident images ----
    {
        const float4* gm = (const float4*)gMimg;
        float4* sw = (float4*)(smem + SM_W);
        for (int i = tid; i < 4096; i += TPB) sw[i] = gm[i];
    }
    for (int idx = tid; idx < 512; idx += TPB) {
        int r = idx >> 2, cp = idx & 3;
        {
            float a = w11[r * 8 + cp * 2], b = w11[r * 8 + cp * 2 + 1];
            uint32_t pl, ph = packsplit(a, b, pl);
            ((uint32_t*)(smem + SM_W1))[r * 4 + cp] = ph;
            ((uint32_t*)(smem + SM_W1 + 2048))[r * 4 + cp] = pl;
        }
        {
            float a = w21[r * 8 + cp * 2], b = w21[r * 8 + cp * 2 + 1];
            uint32_t pl, ph = packsplit(a, b, pl);
            ((uint32_t*)(smem + SM_W1 + 4096))[r * 4 + cp] = ph;
            ((uint32_t*)(smem + SM_W1 + 6144))[r * 4 + cp] = pl;
        }
    }
    if (tid < 128) {
        sC[tid] = b11[tid]; sC[128 + tid] = b21[tid]; sC[256 + tid] = gCvec[tid];
    }
    if (tid == 0) sC[384] = gCvec[128];
    __syncthreads();

    const float c0 = sC[384];
    float B11c[4][2], B21c[4][2], Cc[4][2];
    #pragma unroll
    for (int j = 0; j < 4; j++)
        #pragma unroll
        for (int e = 0; e < 2; e++) {
            int c = n0 + j * 8 + q4 * 2 + e;
            B11c[j][e] = sC[c]; B21c[j][e] = sC[128 + c]; Cc[j][e] = sC[256 + c];
        }
    uint32_t w1f[4][4];
    #pragma unroll
    for (int img = 0; img < 4; img++)
        #pragma unroll
        for (int ng = 0; ng < 2; ng++)
            LDSM2(&w1f[img][ng * 2],
                  sb + SM_W1 + img * 2048 + (uint32_t)(n0 + ng * 16 + (lane & 15)) * 16);

    for (int t = blockIdx.x; t < ntot; t += gridDim.x) {
        __syncthreads();
        if (t < nfwd) {
            do_tile<false>(smem, sb, t, T, center, nullptr,
                           out_vt, out_vc, nullptr, naT,
                           B11c, B21c, Cc, c0, w1f);
        } else {
            do_tile<true>(smem, sb, t - nfwd, l, nullptr, l1_dot,
                          out_vy, nullptr, out_vg, 0,
                          B11c, B21c, Cc, c0, w1f);
        }
    }
}

extern "C" void kernel_launch(void* const* d_in, const int* in_sizes, int n_in,
                              void* d_out, int out_size)
{
    const float* T      = (const float*)d_in[0];
    const float* l      = (const float*)d_in[1];
    const float* l1_dot = (const float*)d_in[2];
    const float* center = (const float*)d_in[3];
    const float* w11 = (const float*)d_in[4];
    const float* b11 = (const float*)d_in[5];
    const float* w21 = (const float*)d_in[6];
    const float* b21 = (const float*)d_in[7];
    const float* w12 = (const float*)d_in[8];
    const float* b12 = (const float*)d_in[9];
    const float* w22 = (const float*)d_in[10];
    const float* b22 = (const float*)d_in[11];
    const float* wout = (const float*)d_in[12];
    float* out = (float*)d_out;

    int nT = in_sizes[0] / 8;   // 65536
    int nL = in_sizes[1] / 8;   // 65536
    int nC = in_sizes[3] / 8;   // 512

    cudaFuncSetAttribute(netall, cudaFuncAttributeMaxDynamicSharedMemorySize, SM_TOTAL);

    float* out_vt = out;
    float* out_vy = out + nT;
    float* out_vg = out + nT + nL;
    float* out_vc = out + nT + 2 * nL;

    int naT = nT / 128;               // 512 T tiles
    int nfwd = naT + nC / 128;        // + 4 center tiles = 516
    int ngrad = nL / 64;              // 1024 grad tiles
    int ntot = nfwd + ngrad;          // 1540

    prep_kernel<<<129, 128>>>(w12, w22, b12, b22, wout);
    netall<<<148, TPB, SM_TOTAL>>>(T, l, l1_dot, center,
                                   w11, b11, w21, b21,
                                   out_vt, out_vy, out_vg, out_vc,
                                   naT, nfwd, ntot);
}

// round 17
// speedup vs baseline: 3.8883x; 1.0269x over previous
#include <cuda_runtime.h>
#include <cuda_bf16.h>
#include <cstdint>

#define TPB 256

__device__ __forceinline__ uint32_t smem_u32(const void* p) {
    uint32_t a;
    asm("{ .reg .u64 t; cvta.to.shared.u64 t, %1; cvt.u32.u64 %0, t; }" : "=r"(a) : "l"(p));
    return a;
}

#define LDSM4(r, addr) \
    asm volatile("ldmatrix.sync.aligned.m8n8.x4.shared.b16 {%0,%1,%2,%3}, [%4];" \
        : "=r"((r)[0]), "=r"((r)[1]), "=r"((r)[2]), "=r"((r)[3]) : "r"(addr))
#define LDSM2(r, addr) \
    asm volatile("ldmatrix.sync.aligned.m8n8.x2.shared.b16 {%0,%1}, [%2];" \
        : "=r"((r)[0]), "=r"((r)[1]) : "r"(addr))

#define MMA16(c, a, b) \
    asm volatile("mma.sync.aligned.m16n8k16.row.col.f32.bf16.bf16.f32 " \
        "{%0,%1,%2,%3}, {%4,%5,%6,%7}, {%8,%9}, {%0,%1,%2,%3};" \
        : "+f"((c)[0]), "+f"((c)[1]), "+f"((c)[2]), "+f"((c)[3]) \
        : "r"((a)[0]), "r"((a)[1]), "r"((a)[2]), "r"((a)[3]), "r"((b)[0]), "r"((b)[1]))
#define MMA8(c, a, b) \
    asm volatile("mma.sync.aligned.m16n8k8.row.col.f32.bf16.bf16.f32 " \
        "{%0,%1,%2,%3}, {%4,%5}, {%6}, {%0,%1,%2,%3};" \
        : "+f"((c)[0]), "+f"((c)[1]), "+f"((c)[2]), "+f"((c)[3]) \
        : "r"((a)[0]), "r"((a)[1]), "r"(b))

// swizzled byte offset in a [rows x 128] bf16 tile, 256B rows, 16B-chunk XOR swizzle
__device__ __forceinline__ uint32_t swz(int row, int col) {
    return (uint32_t)(row * 256 + ((((col >> 3) ^ (row & 7)) & 15) << 4) + (col & 7) * 2);
}

// split a,b into bf16 hi-pair (return) and lo-pair (out param)
__device__ __forceinline__ uint32_t packsplit(float a, float b, uint32_t& lo) {
    __nv_bfloat16 ah = __float2bfloat16_rn(a), bh = __float2bfloat16_rn(b);
    __nv_bfloat16 al = __float2bfloat16_rn(a - __bfloat162float(ah));
    __nv_bfloat16 bl = __float2bfloat16_rn(b - __bfloat162float(bh));
    lo = (uint32_t)__bfloat16_as_ushort(al) | ((uint32_t)__bfloat16_as_ushort(bl) << 16);
    return (uint32_t)__bfloat16_as_ushort(ah) | ((uint32_t)__bfloat16_as_ushort(bh) << 16);
}

// ---------------- device scratch ----------------
__device__ uint32_t gMimg[2][8192];  // M = W1^T diag(wo) W2: [Mh, Ml] 128x128 bf16 swizzled
__device__ float gCvec[129];         // c[128], c0

__global__ void prep_kernel(const float* __restrict__ w12, const float* __restrict__ w22,
                            const float* __restrict__ b12, const float* __restrict__ b22,
                            const float* __restrict__ wout) {
    __shared__ float sWJ[128];
    int j = blockIdx.x, t = threadIdx.x;
    if (j < 128) {
        // image row j holds M[:, j] along k=i:  B[n=j][k=i] = M_ij
        sWJ[t] = wout[t] * w22[t * 128 + j];
        __syncthreads();
        if (t < 64) {
            int i0 = t * 2;
            float m0 = 0.f, m1 = 0.f;
            for (int o = 0; o < 128; o++) {
                float wj = sWJ[o];
                m0 = fmaf(w12[o * 128 + i0], wj, m0);
                m1 = fmaf(w12[o * 128 + i0 + 1], wj, m1);
            }
            uint32_t pl, ph = packsplit(m0, m1, pl);
            gMimg[0][swz(j, i0) >> 2] = ph;
            gMimg[1][swz(j, i0) >> 2] = pl;
        }
    } else {
        float acc = 0.f;
        for (int o = 0; o < 128; o++)
            acc = fmaf(wout[o],
                       fmaf(w12[o * 128 + t], b22[o], w22[o * 128 + t] * b12[o]), acc);
        gCvec[t] = acc;
        if (t == 0) {
            float cc = 0.f;
            for (int o = 0; o < 128; o++) cc = fmaf(wout[o] * b12[o], b22[o], cc);
            gCvec[128] = cc;
        }
    }
}

// ---------------- smem layout (bytes) ----------------
#define SM_W     0          // M images: Mh, Ml (2 x 32768)
#define SM_A     65536      // A images: 64KB (fwd 2x32KB; grad 4x16KB)
#define SM_X     131072     // X images: 4 x 2048
#define SM_W1    139264     // layer-1 W images: 4 x 2048
#define SM_CONST 147456     // b11(512), b21(512), c(512), c0(+pad 512)
#define SM_RED   149504     // sRedV 1024, sRedG 1024
#define SM_YC    151552     // sYC 1024, sDC 1024
#define SM_TOTAL 153600

template <bool GRAD>
__device__ __forceinline__ void do_tile(
    char* smem, uint32_t sb, int tile,
    const float* __restrict__ xa, const float* __restrict__ xb,
    const float* __restrict__ xdot,
    float* __restrict__ outa, float* __restrict__ outb,
    float* __restrict__ out_g, int na,
    const float (&B11c)[4][2], const float (&B21c)[4][2],
    const float (&Cc)[4][2], float c0, const uint32_t (&w1f)[4][4])
{
    const int tid = threadIdx.x;
    const int wid = tid >> 5, lane = tid & 31;
    const int g4 = lane >> 2, q4 = lane & 3;

    constexpr int SPT  = GRAD ? 64 : 128;
    constexpr int MT   = GRAD ? 2 : 4;
    constexpr int AIMG = GRAD ? 16384 : 32768;

    const int wm = wid & 1, wn = wid >> 1;
    const int m0 = wm * (SPT / 2);
    const int n0 = wn * 32;

    float* sRedV = (float*)(smem + SM_RED);
    float* sRedG = sRedV + 256;
    float* sYC   = (float*)(smem + SM_YC);   // [SPT][4] wn-partials of y.c
    float* sDC   = sYC + 256;                // [64][4]  wn-partials of d.c (grad)

    // ---- stage X images (bf16 hi/lo split) ----
    if (tid < 128) {
        const float* xp;
        uint32_t xoff;
        int t;
        if (!GRAD) {
            t = tid;
            xp = (tile < na) ? xa + (size_t)tile * (128 * 8)
                             : xb + (size_t)(tile - na) * (128 * 8);
            xoff = 0;
        } else {
            t = tid & 63;
            xp = (tid < 64) ? xa + (size_t)tile * (64 * 8)
                            : xdot + (size_t)tile * (64 * 8);
            xoff = (tid < 64) ? 0 : 4096;
        }
        const float4* g = (const float4*)(xp + (size_t)t * 8);
        float4 v0 = g[0], v1 = g[1];
        float v[8] = {v0.x, v0.y, v0.z, v0.w, v1.x, v1.y, v1.z, v1.w};
        uint32_t hi[4], lo[4];
        #pragma unroll
        for (int i = 0; i < 4; i++) hi[i] = packsplit(v[2 * i], v[2 * i + 1], lo[i]);
        *(uint4*)(smem + SM_X + xoff + t * 16) = make_uint4(hi[0], hi[1], hi[2], hi[3]);
        *(uint4*)(smem + SM_X + xoff + 2048 + t * 16) = make_uint4(lo[0], lo[1], lo[2], lo[3]);
    }
    __syncthreads();

    // register-resident y (and dy) fragments, same C layout as layer-2 accumulators
    float yv[MT][4][4];
    float dv[GRAD ? MT : 1][4][4];

    // ---- layer 1 via m16n8k8 MMA; gate; y.c / d.c partials; store A images ----
    {
        float z1[MT][4][4], z2[MT][4][4];
        float d1[GRAD ? MT : 1][4][4], d2[GRAD ? MT : 1][4][4];
        #pragma unroll
        for (int mt = 0; mt < MT; mt++)
            #pragma unroll
            for (int j = 0; j < 4; j++)
                #pragma unroll
                for (int e = 0; e < 4; e++) {
                    z1[mt][j][e] = 0.f; z2[mt][j][e] = 0.f;
                    if (GRAD) { d1[mt][j][e] = 0.f; d2[mt][j][e] = 0.f; }
                }
        #pragma unroll
        for (int mt = 0; mt < MT; mt++) {
            uint32_t xh[2], xl[2], xdh[2], xdl[2];
            uint32_t xr = (uint32_t)(m0 + mt * 16 + (lane & 15)) * 16;
            LDSM2(xh, sb + SM_X + xr);
            LDSM2(xl, sb + SM_X + 2048 + xr);
            if (GRAD) {
                LDSM2(xdh, sb + SM_X + 4096 + xr);
                LDSM2(xdl, sb + SM_X + 6144 + xr);
            }
            #pragma unroll
            for (int j = 0; j < 4; j++) {
                MMA8(z1[mt][j], xh, w1f[0][j]);
                MMA8(z1[mt][j], xh, w1f[1][j]);
                MMA8(z1[mt][j], xl, w1f[0][j]);
                MMA8(z2[mt][j], xh, w1f[2][j]);
                MMA8(z2[mt][j], xh, w1f[3][j]);
                MMA8(z2[mt][j], xl, w1f[2][j]);
                if (GRAD) {
                    MMA8(d1[mt][j], xdh, w1f[0][j]);
                    MMA8(d1[mt][j], xdh, w1f[1][j]);
                    MMA8(d1[mt][j], xdl, w1f[0][j]);
                    MMA8(d2[mt][j], xdh, w1f[2][j]);
                    MMA8(d2[mt][j], xdh, w1f[3][j]);
                    MMA8(d2[mt][j], xdl, w1f[2][j]);
                }
            }
        }
        #pragma unroll
        for (int mt = 0; mt < MT; mt++) {
            float yc0 = 0.f, yc1 = 0.f, dc0 = 0.f, dc1 = 0.f;
            #pragma unroll
            for (int j = 0; j < 4; j++) {
                float u1[4], u2[4];
                #pragma unroll
                for (int e = 0; e < 4; e++) {
                    u1[e] = z1[mt][j][e] + B11c[j][e & 1];
                    u2[e] = z2[mt][j][e] + B21c[j][e & 1];
                    yv[mt][j][e] = u1[e] * u2[e];
                }
                yc0 = fmaf(yv[mt][j][0], Cc[j][0], fmaf(yv[mt][j][1], Cc[j][1], yc0));
                yc1 = fmaf(yv[mt][j][2], Cc[j][0], fmaf(yv[mt][j][3], Cc[j][1], yc1));
                int row = m0 + mt * 16 + g4;
                int col = n0 + j * 8 + q4 * 2;
                uint32_t o0 = swz(row, col), o1 = swz(row + 8, col);
                uint32_t l01, h01 = packsplit(yv[mt][j][0], yv[mt][j][1], l01);
                uint32_t l23, h23 = packsplit(yv[mt][j][2], yv[mt][j][3], l23);
                *(uint32_t*)(smem + SM_A + o0) = h01;
                *(uint32_t*)(smem + SM_A + AIMG + o0) = l01;
                *(uint32_t*)(smem + SM_A + o1) = h23;
                *(uint32_t*)(smem + SM_A + AIMG + o1) = l23;
                if (GRAD) {
                    #pragma unroll
                    for (int e = 0; e < 4; e++)
                        dv[mt][j][e] = fmaf(u1[e], d2[mt][j][e], u2[e] * d1[mt][j][e]);
                    dc0 = fmaf(dv[mt][j][0], Cc[j][0], fmaf(dv[mt][j][1], Cc[j][1], dc0));
                    dc1 = fmaf(dv[mt][j][2], Cc[j][0], fmaf(dv[mt][j][3], Cc[j][1], dc1));
                    uint32_t dl01, dh01 = packsplit(dv[mt][j][0], dv[mt][j][1], dl01);
                    uint32_t dl23, dh23 = packsplit(dv[mt][j][2], dv[mt][j][3], dl23);
                    *(uint32_t*)(smem + SM_A + 2 * AIMG + o0) = dh01;
                    *(uint32_t*)(smem + SM_A + 3 * AIMG + o0) = dl01;
                    *(uint32_t*)(smem + SM_A + 2 * AIMG + o1) = dh23;
                    *(uint32_t*)(smem + SM_A + 3 * AIMG + o1) = dl23;
                }
            }
            yc0 += __shfl_xor_sync(0xffffffff, yc0, 1);
            yc0 += __shfl_xor_sync(0xffffffff, yc0, 2);
            yc1 += __shfl_xor_sync(0xffffffff, yc1, 1);
            yc1 += __shfl_xor_sync(0xffffffff, yc1, 2);
            if (GRAD) {
                dc0 += __shfl_xor_sync(0xffffffff, dc0, 1);
                dc0 += __shfl_xor_sync(0xffffffff, dc0, 2);
                dc1 += __shfl_xor_sync(0xffffffff, dc1, 1);
                dc1 += __shfl_xor_sync(0xffffffff, dc1, 2);
            }
            if (q4 == 0) {
                int r = m0 + mt * 16 + g4;
                sYC[r * 4 + wn] = yc0;
                sYC[(r + 8) * 4 + wn] = yc1;
                if (GRAD) { sDC[r * 4 + wn] = dc0; sDC[(r + 8) * 4 + wn] = dc1; }
            }
        }
    }
    __syncthreads();

    // ---- layer 2: P = Y.M (and Q = D.M), bf16 3-term split ----
    float czP[MT][4][4];
    float czQ[GRAD ? MT : 1][4][4];
    #pragma unroll
    for (int mt = 0; mt < MT; mt++)
        #pragma unroll
        for (int j = 0; j < 4; j++)
            #pragma unroll
            for (int e = 0; e < 4; e++) {
                czP[mt][j][e] = 0.f;
                if (GRAD) czQ[mt][j][e] = 0.f;
            }

    #pragma unroll 1
    for (int kt = 0; kt < 8; kt++) {
        const int k0 = kt * 16;
        uint32_t bf[2][2][4];
        {
            int nr = n0 + (lane & 7) + ((lane >> 4) << 3);
            int kc = k0 + ((lane >> 3) & 1) * 8;
            #pragma unroll
            for (int img = 0; img < 2; img++)
                #pragma unroll
                for (int ng = 0; ng < 2; ng++)
                    LDSM4(bf[img][ng], sb + SM_W + img * 32768 + swz(nr + ng * 16, kc));
        }
        #pragma unroll
        for (int mt = 0; mt < MT; mt++) {
            int ar = m0 + mt * 16 + (lane & 7) + ((lane >> 3) & 1) * 8;
            int ac = k0 + (lane >> 4) * 8;
            uint32_t off = swz(ar, ac);
            uint32_t aYh[4], aYl[4], aDh[4], aDl[4];
            LDSM4(aYh, sb + SM_A + off);
            LDSM4(aYl, sb + SM_A + AIMG + off);
            if (GRAD) {
                LDSM4(aDh, sb + SM_A + 2 * AIMG + off);
                LDSM4(aDl, sb + SM_A + 3 * AIMG + off);
            }
            #pragma unroll
            for (int j = 0; j < 4; j++) {
                const int ng = j >> 1, sub = (j & 1) * 2;
                MMA16(czP[mt][j], aYh, (&bf[0][ng][sub]));
                MMA16(czP[mt][j], aYh, (&bf[1][ng][sub]));
                MMA16(czP[mt][j], aYl, (&bf[0][ng][sub]));
                if (GRAD) {
                    MMA16(czQ[mt][j], aDh, (&bf[0][ng][sub]));
                    MMA16(czQ[mt][j], aDh, (&bf[1][ng][sub]));
                    MMA16(czQ[mt][j], aDl, (&bf[0][ng][sub]));
                }
            }
        }
    }

    // ---- epilogue from registers: v = <P,y> (+ y.c + c0); g = <Q,y> + <P,d> (+ d.c) ----
    #pragma unroll
    for (int mt = 0; mt < MT; mt++) {
        float pv0 = 0.f, pv1 = 0.f, pg0 = 0.f, pg1 = 0.f;
        int r0 = m0 + mt * 16 + g4, r1 = r0 + 8;
        #pragma unroll
        for (int j = 0; j < 4; j++) {
            pv0 = fmaf(czP[mt][j][0], yv[mt][j][0], fmaf(czP[mt][j][1], yv[mt][j][1], pv0));
            pv1 = fmaf(czP[mt][j][2], yv[mt][j][2], fmaf(czP[mt][j][3], yv[mt][j][3], pv1));
            if (GRAD) {
                pg0 = fmaf(czQ[mt][j][0], yv[mt][j][0], fmaf(czQ[mt][j][1], yv[mt][j][1], pg0));
                pg0 = fmaf(czP[mt][j][0], dv[mt][j][0], fmaf(czP[mt][j][1], dv[mt][j][1], pg0));
                pg1 = fmaf(czQ[mt][j][2], yv[mt][j][2], fmaf(czQ[mt][j][3], yv[mt][j][3], pg1));
                pg1 = fmaf(czP[mt][j][2], dv[mt][j][2], fmaf(czP[mt][j][3], dv[mt][j][3], pg1));
            }
        }
        pv0 += __shfl_xor_sync(0xffffffff, pv0, 1);
        pv0 += __shfl_xor_sync(0xffffffff, pv0, 2);
        pv1 += __shfl_xor_sync(0xffffffff, pv1, 1);
        pv1 += __shfl_xor_sync(0xffffffff, pv1, 2);
        if (GRAD) {
            pg0 += __shfl_xor_sync(0xffffffff, pg0, 1);
            pg0 += __shfl_xor_sync(0xffffffff, pg0, 2);
            pg1 += __shfl_xor_sync(0xffffffff, pg1, 1);
            pg1 += __shfl_xor_sync(0xffffffff, pg1, 2);
        }
        if (q4 == 0) {
            sRedV[r0 * 4 + wn] = pv0;
            sRedV[r1 * 4 + wn] = pv1;
            if (GRAD) { sRedG[r0 * 4 + wn] = pg0; sRedG[r1 * 4 + wn] = pg1; }
        }
    }
    __syncthreads();

    if (!GRAD) {
        if (tid < 128) {
            float4 vv = *(float4*)&sRedV[tid * 4];
            float4 yy = *(float4*)&sYC[tid * 4];
            float v = vv.x + vv.y + vv.z + vv.w + yy.x + yy.y + yy.z + yy.w + c0;
            float* op = (tile < na) ? outa + (size_t)tile * 128
                                    : outb + (size_t)(tile - na) * 128;
            op[tid] = v;
        }
    } else {
        if (tid < 64) {
            float4 vv = *(float4*)&sRedV[tid * 4];
            float4 yy = *(float4*)&sYC[tid * 4];
            outa[(size_t)tile * 64 + tid] =
                vv.x + vv.y + vv.z + vv.w + yy.x + yy.y + yy.z + yy.w + c0;
        } else if (tid < 128) {
            int t = tid - 64;
            float4 gg = *(float4*)&sRedG[t * 4];
            float4 dd = *(float4*)&sDC[t * 4];
            out_g[(size_t)tile * 64 + t] =
                gg.x + gg.y + gg.z + gg.w + dd.x + dd.y + dd.z + dd.w;
        }
    }
}

__global__ __launch_bounds__(TPB, 1)
void netall(const float* __restrict__ T, const float* __restrict__ l,
            const float* __restrict__ l1_dot, const float* __restrict__ center,
            const float* __restrict__ w11, const float* __restrict__ b11,
            const float* __restrict__ w21, const float* __restrict__ b21,
            float* __restrict__ out_vt, float* __restrict__ out_vy,
            float* __restrict__ out_vg, float* __restrict__ out_vc,
            int naT, int nfwd, int ntot)
{
    extern __shared__ char smem[];
    const uint32_t sb = smem_u32(smem);
    const int tid = threadIdx.x;
    const int wid = tid >> 5, lane = tid & 31;
    const int q4 = lane & 3;
    const int wn = wid >> 1;
    const int n0 = wn * 32;

    float* sC = (float*)(smem + SM_CONST);

    // ---- build resident images ----
    {
        const float4* gm = (const float4*)gMimg;
        float4* sw = (float4*)(smem + SM_W);
        for (int i = tid; i < 4096; i += TPB) sw[i] = gm[i];
    }
    for (int idx = tid; idx < 512; idx += TPB) {
        int r = idx >> 2, cp = idx & 3;
        {
            float a = w11[r * 8 + cp * 2], b = w11[r * 8 + cp * 2 + 1];
            uint32_t pl, ph = packsplit(a, b, pl);
            ((uint32_t*)(smem + SM_W1))[r * 4 + cp] = ph;
            ((uint32_t*)(smem + SM_W1 + 2048))[r * 4 + cp] = pl;
        }
        {
            float a = w21[r * 8 + cp * 2], b = w21[r * 8 + cp * 2 + 1];
            uint32_t pl, ph = packsplit(a, b, pl);
            ((uint32_t*)(smem + SM_W1 + 4096))[r * 4 + cp] = ph;
            ((uint32_t*)(smem + SM_W1 + 6144))[r * 4 + cp] = pl;
        }
    }
    if (tid < 128) {
        sC[tid] = b11[tid]; sC[128 + tid] = b21[tid]; sC[256 + tid] = gCvec[tid];
    }
    if (tid == 0) sC[384] = gCvec[128];
    __syncthreads();

    const float c0 = sC[384];
    float B11c[4][2], B21c[4][2], Cc[4][2];
    #pragma unroll
    for (int j = 0; j < 4; j++)
        #pragma unroll
        for (int e = 0; e < 2; e++) {
            int c = n0 + j * 8 + q4 * 2 + e;
            B11c[j][e] = sC[c]; B21c[j][e] = sC[128 + c]; Cc[j][e] = sC[256 + c];
        }
    uint32_t w1f[4][4];
    #pragma unroll
    for (int img = 0; img < 4; img++)
        #pragma unroll
        for (int ng = 0; ng < 2; ng++)
            LDSM2(&w1f[img][ng * 2],
                  sb + SM_W1 + img * 2048 + (uint32_t)(n0 + ng * 16 + (lane & 15)) * 16);

    for (int t = blockIdx.x; t < ntot; t += gridDim.x) {
        if (t < nfwd) {
            do_tile<false>(smem, sb, t, T, center, nullptr,
                           out_vt, out_vc, nullptr, naT,
                           B11c, B21c, Cc, c0, w1f);
        } else {
            do_tile<true>(smem, sb, t - nfwd, l, nullptr, l1_dot,
                          out_vy, nullptr, out_vg, 0,
                          B11c, B21c, Cc, c0, w1f);
        }
    }
}

extern "C" void kernel_launch(void* const* d_in, const int* in_sizes, int n_in,
                              void* d_out, int out_size)
{
    const float* T      = (const float*)d_in[0];
    const float* l      = (const float*)d_in[1];
    const float* l1_dot = (const float*)d_in[2];
    const float* center = (const float*)d_in[3];
    const float* w11 = (const float*)d_in[4];
    const float* b11 = (const float*)d_in[5];
    const float* w21 = (const float*)d_in[6];
    const float* b21 = (const float*)d_in[7];
    const float* w12 = (const float*)d_in[8];
    const float* b12 = (const float*)d_in[9];
    const float* w22 = (const float*)d_in[10];
    const float* b22 = (const float*)d_in[11];
    const float* wout = (const float*)d_in[12];
    float* out = (float*)d_out;

    int nT = in_sizes[0] / 8;   // 65536
    int nL = in_sizes[1] / 8;   // 65536
    int nC = in_sizes[3] / 8;   // 512

    cudaFuncSetAttribute(netall, cudaFuncAttributeMaxDynamicSharedMemorySize, SM_TOTAL);

    float* out_vt = out;
    float* out_vy = out + nT;
    float* out_vg = out + nT + nL;
    float* out_vc = out + nT + 2 * nL;

    int naT = nT / 128;               // 512 T tiles
    int nfwd = naT + nC / 128;        // + 4 center tiles = 516
    int ngrad = nL / 64;              // 1024 grad tiles
    int ntot = nfwd + ngrad;          // 1540

    prep_kernel<<<129, 128>>>(w12, w22, b12, b22, wout);
    netall<<<148, TPB, SM_TOTAL>>>(T, l, l1_dot, center,
                                   w11, b11, w21, b21,
                                   out_vt, out_vy, out_vg, out_vc,
                                   naT, nfwd, ntot);
}